// round 13
// baseline (speedup 1.0000x reference)
#include <cuda_runtime.h>
#include <cstdint>

#define NIMG  4
#define CCH   80
#define TOPN  500
#define NCAND 1500
#define CAP0 524288
#define CAP1 131072
#define CAP2 65536
#define CAPI (CAP0+CAP1+CAP2)
#define BOX_LOGIT_THRESH (-2.9444389791664403f)

__device__ __align__(16) unsigned long long g_cand[NIMG * CAPI];
__device__ unsigned int       g_cnt[NIMG * 3];
__device__ unsigned long long g_top[NIMG * NCAND];
__device__ float g_x1[NIMG*NCAND], g_y1[NIMG*NCAND], g_x2[NIMG*NCAND], g_y2[NIMG*NCAND];
__device__ int   g_lb[NIMG*NCAND];
__device__ unsigned char g_vd[NIMG*NCAND];

__constant__ int c_cap[3]  = {CAP0, CAP1, CAP2};
__constant__ int c_loff[3] = {0, CAP0, CAP0 + CAP1};

__device__ __forceinline__ float sigm(float x) {
    if (x >= 0.f) return 1.f / (1.f + expf(-x));
    float e = expf(x); return e / (1.f + e);
}

// hybrid bitonic descending sort, SZ elements, 1024 threads.
template<int SZ>
__device__ void bitonic_desc_h(unsigned long long* a) {
    constexpr int E = SZ / 1024;
    int tid = threadIdx.x;
    unsigned long long v[E];
    #pragma unroll
    for (int m = 0; m < E; m++) v[m] = a[tid + (m << 10)];
    #pragma unroll
    for (int k = 2; k <= 32; k <<= 1) {
        #pragma unroll
        for (int j = k >> 1; j >= 1; j >>= 1) {
            #pragma unroll
            for (int m = 0; m < E; m++) {
                int t = tid + (m << 10);
                unsigned long long pv = __shfl_xor_sync(0xFFFFFFFFu, v[m], j);
                bool keepmax = (((t & k) == 0) == ((t & j) == 0));
                if (keepmax == (pv > v[m])) v[m] = pv;
            }
        }
    }
    #pragma unroll
    for (int m = 0; m < E; m++) a[tid + (m << 10)] = v[m];
    __syncthreads();
    for (int k = 64; k <= SZ; k <<= 1) {
        for (int j = k >> 1; j >= 32; j >>= 1) {
            #pragma unroll
            for (int m = 0; m < E; m++) {
                int t = tid + (m << 10);
                int ixj = t ^ j;
                if (ixj > t) {
                    unsigned long long u = a[t], w = a[ixj];
                    bool sw = ((t & k) == 0) ? (u < w) : (u > w);
                    if (sw) { a[t] = w; a[ixj] = u; }
                }
            }
            __syncthreads();
        }
        #pragma unroll
        for (int m = 0; m < E; m++) v[m] = a[tid + (m << 10)];
        #pragma unroll
        for (int j = 16; j >= 1; j >>= 1) {
            #pragma unroll
            for (int m = 0; m < E; m++) {
                int t = tid + (m << 10);
                unsigned long long pv = __shfl_xor_sync(0xFFFFFFFFu, v[m], j);
                bool keepmax = (((t & k) == 0) == ((t & j) == 0));
                if (keepmax == (pv > v[m])) v[m] = pv;
            }
        }
        #pragma unroll
        for (int m = 0; m < E; m++) a[tid + (m << 10)] = v[m];
        __syncthreads();
    }
}

// warp-aggregated candidate emit (up to 8 per thread)
template<int LVL, int CAPL, int LOFF>
__device__ __forceinline__ void emit8(int n, const unsigned* sbv, const int* rrv, int cnt) {
    int lane = threadIdx.x & 31;
    unsigned cinc = (unsigned)cnt;
    #pragma unroll
    for (int off = 1; off < 32; off <<= 1) {
        unsigned t = __shfl_up_sync(0xFFFFFFFFu, cinc, off);
        if (lane >= off) cinc += t;
    }
    unsigned total = __shfl_sync(0xFFFFFFFFu, cinc, 31);
    if (total == 0u) return;
    int b = n * 3 + LVL;
    unsigned base = 0;
    if (lane == 0) base = atomicAdd(&g_cnt[b], total);
    base = __shfl_sync(0xFFFFFFFFu, base, 0);
    unsigned pre = cinc - (unsigned)cnt;
    #pragma unroll
    for (int k = 0; k < 8; k++) {
        if (k >= cnt) break;
        unsigned slot = base + pre + (unsigned)k;
        if (slot < (unsigned)CAPL)
            g_cand[(size_t)n * CAPI + LOFF + slot] =
                ((unsigned long long)sbv[k] << 32) | (unsigned)(~rrv[k]);
    }
}

#define CAND_CHECK(px, cl, gc, m) do {                                       \
    if ((px) && ((gc) >= (m))) {                                             \
        float sc_ = sqrtf(sigm(cl) * sigm(gc));                              \
        sbv[cnt] = __float_as_uint(sc_); rrv[cnt] = rb + _k; cnt++;          \
    } _k++;                                                                  \
} while (0)

#define STENCIL8_BODY(s0, s1, s2)                                            \
    float4 uA = *(const float4*)(s0), uB = *(const float4*)((s0) + 4);       \
    float4 cA = *(const float4*)(s1), cB = *(const float4*)((s1) + 4);       \
    float4 dA = *(const float4*)(s2), dB = *(const float4*)((s2) + 4);       \
    float cmL = hasL ? fmaxf(fmaxf((s0)[-1], (s1)[-1]), (s2)[-1]) : 0.f;     \
    float cmR = hasR ? fmaxf(fmaxf((s0)[8],  (s1)[8]),  (s2)[8])  : 0.f;     \
    float4 mA, mB;                                                           \
    mA.x = fmaxf(fmaxf(uA.x, cA.x), dA.x);                                   \
    mA.y = fmaxf(fmaxf(uA.y, cA.y), dA.y);                                   \
    mA.z = fmaxf(fmaxf(uA.z, cA.z), dA.z);                                   \
    mA.w = fmaxf(fmaxf(uA.w, cA.w), dA.w);                                   \
    mB.x = fmaxf(fmaxf(uB.x, cB.x), dB.x);                                   \
    mB.y = fmaxf(fmaxf(uB.y, cB.y), dB.y);                                   \
    mB.z = fmaxf(fmaxf(uB.z, cB.z), dB.z);                                   \
    mB.w = fmaxf(fmaxf(uB.w, cB.w), dB.w);                                   \
    float m0 = fmaxf(fmaxf(cmL,  mA.x), mA.y);                               \
    float m1 = fmaxf(fmaxf(mA.x, mA.y), mA.z);                               \
    float m2 = fmaxf(fmaxf(mA.y, mA.z), mA.w);                               \
    float m3 = fmaxf(fmaxf(mA.z, mA.w), mB.x);                               \
    float m4 = fmaxf(fmaxf(mA.w, mB.x), mB.y);                               \
    float m5 = fmaxf(fmaxf(mB.x, mB.y), mB.z);                               \
    float m6 = fmaxf(fmaxf(mB.y, mB.z), mB.w);                               \
    float m7 = fmaxf(fmaxf(mB.z, mB.w), cmR);                                \
    int _k = 0;                                                              \
    CAND_CHECK(p0, clA.x, cA.x, m0);                                         \
    CAND_CHECK(p1, clA.y, cA.y, m1);                                         \
    CAND_CHECK(p2, clA.z, cA.z, m2);                                         \
    CAND_CHECK(p3, clA.w, cA.w, m3);                                         \
    CAND_CHECK(p4, clB.x, cB.x, m4);                                         \
    CAND_CHECK(p5, clB.y, cB.y, m5);                                         \
    CAND_CHECK(p6, clB.z, cB.z, m6);                                         \
    CAND_CHECK(p7, clB.w, cB.w, m7);

template<int H, int W, int R, int LVL, int CAPL, int LOFF>
__device__ __forceinline__ void score_tile8(const float* __restrict__ cls,
                                            const float* __restrict__ gau,
                                            float* sg, int bid) {
    constexpr int hw  = H * W;
    constexpr int RPC = H / R;
    constexpr int w4  = W / 4;
    constexpr int NF4 = (R + 2) * w4;
    int tid = threadIdx.x;
    int cb  = bid / RPC;
    int ry  = (bid - cb * RPC) * R;
    int n   = cb / CCH;
    size_t base = (size_t)cb * hw;

    for (int i = tid; i < NF4; i += 256) {
        int row = i / w4;
        int c4  = i - row * w4;
        int gy  = min(max(ry - 1 + row, 0), H - 1);
        ((float4*)sg)[i] = *(const float4*)(gau + base + (size_t)gy * W + c4 * 4);
    }
    __syncthreads();

    int t  = tid * 8;
    int lr = t / W;
    int x0 = t - lr * W;
    int y  = ry + lr;
    int sr = lr + 1;

    const float* cp = cls + base + (size_t)y * W + x0;
    float4 clA = *(const float4*)cp;
    float4 clB = *(const float4*)(cp + 4);
    bool iy = (y > 0) & (y < H - 1);
    bool hasL = x0 > 0, hasR = x0 < W - 8;
    bool p0 = iy && hasL && (clA.x > BOX_LOGIT_THRESH);
    bool p1 = iy && (clA.y > BOX_LOGIT_THRESH);
    bool p2 = iy && (clA.z > BOX_LOGIT_THRESH);
    bool p3 = iy && (clA.w > BOX_LOGIT_THRESH);
    bool p4 = iy && (clB.x > BOX_LOGIT_THRESH);
    bool p5 = iy && (clB.y > BOX_LOGIT_THRESH);
    bool p6 = iy && (clB.z > BOX_LOGIT_THRESH);
    bool p7 = iy && hasR && (clB.w > BOX_LOGIT_THRESH);

    unsigned sbv[8]; int rrv[8]; int cnt = 0;
    int rb = (cb - n * CCH) * hw + y * W + x0;

    if (p0 | p1 | p2 | p3 | p4 | p5 | p6 | p7) {
        const float* s0 = sg + (sr - 1) * W + x0;
        const float* s1 = sg + sr * W + x0;
        const float* s2 = sg + (sr + 1) * W + x0;
        STENCIL8_BODY(s0, s1, s2)
    }
    emit8<LVL, CAPL, LOFF>(n, sbv, rrv, cnt);
}

template<int H, int W, int LVL, int CAPL, int LOFF>
__device__ __forceinline__ void score_body8(const float* __restrict__ cls,
                                            const float* __restrict__ gau, int bid) {
    constexpr int hw  = H * W;
    constexpr int CHW = CCH * hw;
    constexpr int OPI = CHW / 8;
    int q   = bid * 256 + threadIdx.x;
    int n   = q / OPI;
    int pix = q * 8;
    int r   = pix - n * CHW;
    int pp  = r % hw;
    int y   = pp / W;
    int x0  = pp & (W - 1);

    const float* cp = cls + (size_t)pix;
    float4 clA = *(const float4*)cp;
    float4 clB = *(const float4*)(cp + 4);
    bool iy = (y > 0) & (y < H - 1);
    bool hasL = x0 > 0, hasR = x0 < W - 8;
    bool p0 = iy && hasL && (clA.x > BOX_LOGIT_THRESH);
    bool p1 = iy && (clA.y > BOX_LOGIT_THRESH);
    bool p2 = iy && (clA.z > BOX_LOGIT_THRESH);
    bool p3 = iy && (clA.w > BOX_LOGIT_THRESH);
    bool p4 = iy && (clB.x > BOX_LOGIT_THRESH);
    bool p5 = iy && (clB.y > BOX_LOGIT_THRESH);
    bool p6 = iy && (clB.z > BOX_LOGIT_THRESH);
    bool p7 = iy && hasR && (clB.w > BOX_LOGIT_THRESH);

    unsigned sbv[8]; int rrv[8]; int cnt = 0;
    int rb = r;

    if (p0 | p1 | p2 | p3 | p4 | p5 | p6 | p7) {
        const float* Gb = gau + (size_t)(pix - pp);
        const float* s0 = Gb + pp - W;
        const float* s1 = Gb + pp;
        const float* s2 = Gb + pp + W;
        STENCIL8_BODY(s0, s1, s2)
    }
    emit8<LVL, CAPL, LOFF>(n, sbv, rrv, cnt);
}

__global__ void __launch_bounds__(256) k_score_all(
    const float* __restrict__ c0, const float* __restrict__ g0,
    const float* __restrict__ c1, const float* __restrict__ g1,
    const float* __restrict__ c2, const float* __restrict__ g2) {
    __shared__ __align__(16) float sg[10 * 256];
    int bid = blockIdx.x;
    if (bid < 6400)       score_tile8<160,256,8, 0,CAP0,0>   (c0, g0, sg, bid);
    else if (bid < 8000)  score_tile8<80, 128,16,1,CAP1,CAP0>(c1, g1, sg, bid - 6400);
    else                  score_body8<40, 64, 2,CAP2,CAP0+CAP1>(c2, g2, bid - 8000);
}

// top-500 select: sampling-based pivot; sorted samples snapshot to registers,
// sel buffer reused for both sample sort and collection (32KB total smem)
__global__ void __launch_bounds__(1024) k_select(const float* __restrict__ g0,
                                                 const float* __restrict__ g1,
                                                 const float* __restrict__ g2) {
    int b = blockIdx.x;
    int n = b / 3, lvl = b % 3;
    __shared__ unsigned long long sel[4096];
    __shared__ unsigned long long sP;
    __shared__ unsigned int sM;
    int tid = threadIdx.x;

    unsigned cnt = min(g_cnt[b], (unsigned)c_cap[lvl]);
    const unsigned long long* cand = &g_cand[(size_t)n * CAPI + c_loff[lvl]];
    __syncthreads();
    if (tid == 0) { g_cnt[b] = 0; sM = 0; }     // reset for next graph replay

    unsigned mFinal;
    if (cnt <= 4096u) {
        for (unsigned i = tid; i < 4096u; i += 1024u)
            sel[i] = (i < cnt) ? cand[i] : 0ull;
        mFinal = cnt;
        __syncthreads();
    } else {
        // gather 4096 strided samples (distinct indices -> distinct keys), sort in sel
        #pragma unroll
        for (int m = 0; m < 4; m++) {
            unsigned i = tid + (m << 10);
            unsigned idx = (unsigned)(((unsigned long long)i * cnt) >> 12);
            sel[i] = cand[idx];
        }
        __syncthreads();
        bitonic_desc_h<4096>(sel);   // descending

        // snapshot sorted samples to registers; sel becomes the collect buffer
        unsigned long long sv[4];
        #pragma unroll
        for (int m = 0; m < 4; m++) sv[m] = sel[tid + (m << 10)];
        __syncthreads();

        const ulonglong2* cand2 = (const ulonglong2*)cand;
        unsigned half = cnt >> 1;
        bool odd = (cnt & 1u) != 0u;

        // binary search on sample rank; pivot = sorted_samples[r]
        int r = (int)(2500ull * 4096ull / cnt);
        if (r < 0) r = 0; if (r > 4095) r = 4095;
        int rmin = -1, rmax = 4096;
        unsigned mm = 0;
        for (int iter = 0; iter < 16; iter++) {
            if (tid == (r & 1023)) sP = sv[r >> 10];
            if (tid == 0) sM = 0;
            __syncthreads();
            unsigned long long P = sP;
            for (unsigned i = tid; i < half; i += 1024u) {
                ulonglong2 kk = cand2[i];
                if (kk.x >= P) {
                    unsigned p = atomicAdd(&sM, 1u);
                    if (p < 4096u) sel[p] = kk.x;
                }
                if (kk.y >= P) {
                    unsigned p = atomicAdd(&sM, 1u);
                    if (p < 4096u) sel[p] = kk.y;
                }
            }
            if (tid == 0 && odd) {
                unsigned long long kz = cand[cnt - 1];
                if (kz >= P) {
                    unsigned p = atomicAdd(&sM, 1u);
                    if (p < 4096u) sel[p] = kz;
                }
            }
            __syncthreads();
            mm = sM;
            if (mm >= (unsigned)TOPN && mm <= 4096u) break;
            if (mm < (unsigned)TOPN) rmin = r; else rmax = r;
            int nr = (rmin + rmax) >> 1;
            if (nr <= rmin) nr = rmin + 1;
            if (nr >= rmax) nr = rmax - 1;
            if (nr < 0 || nr > 4095 || nr == r) break;   // stuck (should not happen)
            r = nr;
            __syncthreads();
        }
        mFinal = min(mm, 4096u);
        for (unsigned i = tid; i < 4096u; i += 1024u)
            if (i >= mFinal) sel[i] = 0ull;
        __syncthreads();
    }

    bitonic_desc_h<4096>(sel);

    if (tid < TOPN) {
        int t = n * NCAND + lvl * TOPN + tid;
        unsigned long long key = sel[tid];
        g_top[t] = key;

        int H, W, step; const float* G;
        if (lvl == 0)      { H = 160; W = 256; step = 8;  G = g0; }
        else if (lvl == 1) { H = 80;  W = 128; step = 16; G = g1; }
        else               { H = 40;  W = 64;  step = 32; G = g2; }
        float sc = __uint_as_float((unsigned)(key >> 32));
        unsigned flat = ~(unsigned)key;
        int hw = H * W;
        if (!(sc > 0.f) || flat >= (unsigned)(CCH * hw)) {
            g_x1[t]=0.f; g_y1[t]=0.f; g_x2[t]=0.f; g_y2[t]=0.f; g_lb[t]=1; g_vd[t]=0;
        } else {
            int c = (int)(flat / hw);
            int rem = (int)(flat - (unsigned)c * hw);
            int y = rem / W, x = rem - y * W;
            const float* Bp = G + ((size_t)(n * CCH + c)) * hw;
            auto LV = [&](int yy, int xx) -> float {
                yy = min(max(yy, 0), H - 1);
                xx = min(max(xx, 0), W - 1);
                return log1pf(expf(-Bp[yy * W + xx])) * 0.125f;
            };
            float l0 = LV(y, x);
            float lxp = LV(y, x+1), lxm = LV(y, x-1);
            float lyp = LV(y+1, x), lym = LV(y-1, x);
            float Ax = (lxp + lxm - 2.f * l0) * 0.5f;
            float Ay = (lyp + lym - 2.f * l0) * 0.5f;
            bool px = Ax > 1e-8f, py = Ay > 1e-8f;
            float Axs = px ? Ax : 1.f, Ays = py ? Ay : 1.f;
            float mux = (float)x - (lxp - lxm) / (4.f * Axs);
            float muy = (float)y - (lyp - lym) / (4.f * Ays);
            float wb = (px ? rsqrtf(2.f * Axs) : 0.f) * (float)step;
            float hb = (py ? rsqrtf(2.f * Ays) : 0.f) * (float)step;
            float x1 = mux * (float)step - 0.5f * wb + (float)(step - 1) * 0.5f;
            float y1 = muy * (float)step - 0.5f * hb + (float)(step - 1) * 0.5f;
            bool vd = (wb > 0.f) && (hb > 0.f);
            float x2 = x1 + wb - 1.f, y2 = y1 + hb - 1.f;
            g_x1[t] = fminf(fmaxf(x1, 0.f), 2047.f);
            g_x2[t] = fminf(fmaxf(x2, 0.f), 2047.f);
            g_y1[t] = fminf(fmaxf(y1, 0.f), 1279.f);
            g_y2[t] = fminf(fmaxf(y2, 0.f), 1279.f);
            g_lb[t] = c + 1; g_vd[t] = vd ? 1 : 0;
        }
    }
}

// per-image NMS: hybrid sort, then exact per-class greedy (one warp per class)
__global__ void __launch_bounds__(1024) k_nms(float* __restrict__ out) {
    __shared__ unsigned long long skey[2048];
    __shared__ float bx1[NCAND], by1[NCAND], bx2[NCAND], by2[NCAND];
    __shared__ short slb[NCAND];
    __shared__ unsigned char keep[NCAND];
    __shared__ short cls_list[NCAND];
    __shared__ int   ofs[82];
    __shared__ int   s_ti[100];
    int n = blockIdx.x, tid = threadIdx.x;
    int w = tid >> 5, lane = tid & 31;

    for (int p = tid; p < 2048; p += 1024) {
        unsigned long long kk = 0ull;
        if (p < NCAND) {
            int gi = n * NCAND + p;
            float sc = __uint_as_float((unsigned)(g_top[gi] >> 32));
            float sv = g_vd[gi] ? sc : -1.f;
            unsigned bits = __float_as_uint(sv);
            unsigned ord = (bits & 0x80000000u) ? ~bits : (bits | 0x80000000u);
            kk = ((unsigned long long)ord << 32) | (0xFFFFFFFFu - (unsigned)p);
        }
        skey[p] = kk;
    }
    __syncthreads();
    bitonic_desc_h<2048>(skey);

    for (int p = tid; p < NCAND; p += 1024) {
        int pos = (int)(0xFFFFFFFFu - (unsigned)skey[p]);
        int gi = n * NCAND + pos;
        bx1[p]=g_x1[gi]; by1[p]=g_y1[gi]; bx2[p]=g_x2[gi]; by2[p]=g_y2[gi];
        slb[p]=(short)g_lb[gi]; keep[p]=g_vd[gi];
    }
    if (tid < 82) ofs[tid] = 0;
    __syncthreads();

    for (int p = tid; p < NCAND; p += 1024)
        if (keep[p]) atomicAdd((unsigned*)&ofs[slb[p]], 1u);
    __syncthreads();
    if (tid == 0) {
        int acc = 0;
        for (int c = 1; c <= 80; c++) { int v = ofs[c]; ofs[c] = acc; acc += v; }
        ofs[81] = acc;
        ofs[0]  = 0;
    }
    __syncthreads();

    for (int lbl = w + 1; lbl <= 80; lbl += 32) {
        int start = ofs[lbl];
        int fill = 0;
        for (int base = 0; base < NCAND; base += 32) {
            int p = base + lane;
            bool match = (p < NCAND) && keep[p] && (slb[p] == (short)lbl);
            unsigned bal = __ballot_sync(0xFFFFFFFFu, match);
            if (match) {
                int pre = __popc(bal & ((1u << lane) - 1u));
                cls_list[start + fill + pre] = (short)p;
            }
            fill += __popc(bal);
        }
    }
    __syncthreads();

    for (int lbl = w + 1; lbl <= 80; lbl += 32) {
        int start = ofs[lbl];
        int k = ofs[lbl + 1] - start;
        if (k < 2) continue;
        for (int t0 = 0; t0 < k; t0 += 32) {
            int e = t0 + lane;
            bool in = e < k;
            int idx = in ? (int)cls_list[start + e] : 0;
            float x1 = 0, y1 = 0, x2 = 0, y2 = 0, ar = 1.f;
            bool alive = false;
            if (in) {
                x1 = bx1[idx]; y1 = by1[idx]; x2 = bx2[idx]; y2 = by2[idx];
                ar = (x2 - x1 + 1.f) * (y2 - y1 + 1.f);
                alive = keep[idx] != 0;
            }
            if (alive) {
                for (int qe = 0; qe < t0; qe++) {
                    int qi = (int)cls_list[start + qe];
                    if (!keep[qi]) continue;
                    float qx1 = bx1[qi], qy1 = by1[qi], qx2 = bx2[qi], qy2 = by2[qi];
                    float iw = fmaxf(fminf(x2, qx2) - fmaxf(x1, qx1) + 1.f, 0.f);
                    float ih = fmaxf(fminf(y2, qy2) - fmaxf(y1, qy1) + 1.f, 0.f);
                    float inter = iw * ih;
                    float qar = (qx2 - qx1 + 1.f) * (qy2 - qy1 + 1.f);
                    if (inter / (ar + qar - inter + 1e-9f) > 0.5f) { alive = false; break; }
                }
            }
            int lim = min(32, k - t0);
            unsigned sup = 0;
            for (int m = 0; m < lim - 1; m++) {
                float mx1 = __shfl_sync(0xFFFFFFFFu, x1, m);
                float my1 = __shfl_sync(0xFFFFFFFFu, y1, m);
                float mx2 = __shfl_sync(0xFFFFFFFFu, x2, m);
                float my2 = __shfl_sync(0xFFFFFFFFu, y2, m);
                float mar = __shfl_sync(0xFFFFFFFFu, ar, m);
                if (in && m < lane) {
                    float iw = fmaxf(fminf(x2, mx2) - fmaxf(x1, mx1) + 1.f, 0.f);
                    float ih = fmaxf(fminf(y2, my2) - fmaxf(y1, my1) + 1.f, 0.f);
                    float inter = iw * ih;
                    if (inter / (ar + mar - inter + 1e-9f) > 0.5f) sup |= (1u << m);
                }
            }
            for (int m = 0; m < lim - 1; m++) {
                unsigned bal = __ballot_sync(0xFFFFFFFFu, alive);
                if (lane > m && ((bal >> m) & 1u) && ((sup >> m) & 1u)) alive = false;
            }
            if (in) keep[idx] = alive ? 1 : 0;
        }
    }
    __syncthreads();

    if (tid < 32) {
        int cnt = 0;
        for (int pass = 0; pass < 2; pass++) {
            for (int b2 = 0; b2 < NCAND && cnt < 100; b2 += 32) {
                int i2 = b2 + lane;
                bool pr = (i2 < NCAND) && ((pass == 0) ? (keep[i2] != 0) : (keep[i2] == 0));
                unsigned ww = __ballot_sync(0xFFFFFFFFu, pr);
                int pre = __popc(ww & ((1u << lane) - 1u));
                if (pr && cnt + pre < 100) s_ti[cnt + pre] = i2;
                cnt += __popc(ww);
            }
            if (cnt > 100) cnt = 100;
        }
    }
    __syncthreads();

    if (tid < 100) {
        int p = s_ti[tid];
        unsigned ord = (unsigned)(skey[p] >> 32);
        float s = (ord & 0x80000000u) ? __uint_as_float(ord ^ 0x80000000u)
                                      : __uint_as_float(~ord);
        float tv = keep[p] ? s : -1.f;
        out[n*400 + tid*4 + 0] = bx1[p];
        out[n*400 + tid*4 + 1] = by1[p];
        out[n*400 + tid*4 + 2] = bx2[p];
        out[n*400 + tid*4 + 3] = by2[p];
        out[1600 + n*100 + tid] = tv;
        out[2000 + n*100 + tid] = (float)slb[p];
        out[2400 + n*100 + tid] = (tv > 0.f) ? 1.f : 0.f;
    }
}

extern "C" void kernel_launch(void* const* d_in, const int* in_sizes, int n_in,
                              void* d_out, int out_size) {
    const float *cls[3], *gau[3];
    if (in_sizes[0] == in_sizes[1]) {          // interleaved
        cls[0]=(const float*)d_in[0]; gau[0]=(const float*)d_in[1];
        cls[1]=(const float*)d_in[2]; gau[1]=(const float*)d_in[3];
        cls[2]=(const float*)d_in[4]; gau[2]=(const float*)d_in[5];
    } else {                                   // grouped
        cls[0]=(const float*)d_in[0]; cls[1]=(const float*)d_in[1]; cls[2]=(const float*)d_in[2];
        gau[0]=(const float*)d_in[3]; gau[1]=(const float*)d_in[4]; gau[2]=(const float*)d_in[5];
    }
    float* out = (float*)d_out;

    k_score_all<<<8400, 256>>>(cls[0], gau[0], cls[1], gau[1], cls[2], gau[2]);
    k_select<<<NIMG * 3, 1024>>>(gau[0], gau[1], gau[2]);
    k_nms<<<NIMG, 1024>>>(out);
}

// round 14
// speedup vs baseline: 1.1332x; 1.1332x over previous
#include <cuda_runtime.h>
#include <cstdint>

#define NIMG  4
#define CCH   80
#define TOPN  500
#define NCAND 1500
#define CAP0 524288
#define CAP1 131072
#define CAP2 65536
#define CAPI (CAP0+CAP1+CAP2)
#define BOX_LOGIT_THRESH (-2.9444389791664403f)

__device__ __align__(16) unsigned long long g_cand[NIMG * CAPI];
__device__ unsigned int       g_cnt[NIMG * 3];
__device__ unsigned long long g_top[NIMG * NCAND];
__device__ float g_x1[NIMG*NCAND], g_y1[NIMG*NCAND], g_x2[NIMG*NCAND], g_y2[NIMG*NCAND];
__device__ int   g_lb[NIMG*NCAND];
__device__ unsigned char g_vd[NIMG*NCAND];

__constant__ int c_cap[3]  = {CAP0, CAP1, CAP2};
__constant__ int c_loff[3] = {0, CAP0, CAP0 + CAP1};

__device__ __forceinline__ float sigm(float x) {
    if (x >= 0.f) return 1.f / (1.f + expf(-x));
    float e = expf(x); return e / (1.f + e);
}

// hybrid bitonic descending sort, SZ elements, 1024 threads.
template<int SZ>
__device__ void bitonic_desc_h(unsigned long long* a) {
    constexpr int E = SZ / 1024;
    int tid = threadIdx.x;
    unsigned long long v[E];
    #pragma unroll
    for (int m = 0; m < E; m++) v[m] = a[tid + (m << 10)];
    #pragma unroll
    for (int k = 2; k <= 32; k <<= 1) {
        #pragma unroll
        for (int j = k >> 1; j >= 1; j >>= 1) {
            #pragma unroll
            for (int m = 0; m < E; m++) {
                int t = tid + (m << 10);
                unsigned long long pv = __shfl_xor_sync(0xFFFFFFFFu, v[m], j);
                bool keepmax = (((t & k) == 0) == ((t & j) == 0));
                if (keepmax == (pv > v[m])) v[m] = pv;
            }
        }
    }
    #pragma unroll
    for (int m = 0; m < E; m++) a[tid + (m << 10)] = v[m];
    __syncthreads();
    for (int k = 64; k <= SZ; k <<= 1) {
        for (int j = k >> 1; j >= 32; j >>= 1) {
            #pragma unroll
            for (int m = 0; m < E; m++) {
                int t = tid + (m << 10);
                int ixj = t ^ j;
                if (ixj > t) {
                    unsigned long long u = a[t], w = a[ixj];
                    bool sw = ((t & k) == 0) ? (u < w) : (u > w);
                    if (sw) { a[t] = w; a[ixj] = u; }
                }
            }
            __syncthreads();
        }
        #pragma unroll
        for (int m = 0; m < E; m++) v[m] = a[tid + (m << 10)];
        #pragma unroll
        for (int j = 16; j >= 1; j >>= 1) {
            #pragma unroll
            for (int m = 0; m < E; m++) {
                int t = tid + (m << 10);
                unsigned long long pv = __shfl_xor_sync(0xFFFFFFFFu, v[m], j);
                bool keepmax = (((t & k) == 0) == ((t & j) == 0));
                if (keepmax == (pv > v[m])) v[m] = pv;
            }
        }
        #pragma unroll
        for (int m = 0; m < E; m++) a[tid + (m << 10)] = v[m];
        __syncthreads();
    }
}

// warp-aggregated candidate emit (up to 8 per thread)
template<int LVL, int CAPL, int LOFF>
__device__ __forceinline__ void emit8(int n, const unsigned* sbv, const int* rrv, int cnt) {
    int lane = threadIdx.x & 31;
    unsigned cinc = (unsigned)cnt;
    #pragma unroll
    for (int off = 1; off < 32; off <<= 1) {
        unsigned t = __shfl_up_sync(0xFFFFFFFFu, cinc, off);
        if (lane >= off) cinc += t;
    }
    unsigned total = __shfl_sync(0xFFFFFFFFu, cinc, 31);
    if (total == 0u) return;
    int b = n * 3 + LVL;
    unsigned base = 0;
    if (lane == 0) base = atomicAdd(&g_cnt[b], total);
    base = __shfl_sync(0xFFFFFFFFu, base, 0);
    unsigned pre = cinc - (unsigned)cnt;
    #pragma unroll
    for (int k = 0; k < 8; k++) {
        if (k >= cnt) break;
        unsigned slot = base + pre + (unsigned)k;
        if (slot < (unsigned)CAPL)
            g_cand[(size_t)n * CAPI + LOFF + slot] =
                ((unsigned long long)sbv[k] << 32) | (unsigned)(~rrv[k]);
    }
}

#define CAND_CHECK(px, cl, gc, m) do {                                       \
    if ((px) && ((gc) >= (m))) {                                             \
        float sc_ = sqrtf(sigm(cl) * sigm(gc));                              \
        sbv[cnt] = __float_as_uint(sc_); rrv[cnt] = rb + _k; cnt++;          \
    } _k++;                                                                  \
} while (0)

#define STENCIL8_BODY(s0, s1, s2)                                            \
    float4 uA = *(const float4*)(s0), uB = *(const float4*)((s0) + 4);       \
    float4 cA = *(const float4*)(s1), cB = *(const float4*)((s1) + 4);       \
    float4 dA = *(const float4*)(s2), dB = *(const float4*)((s2) + 4);       \
    float cmL = hasL ? fmaxf(fmaxf((s0)[-1], (s1)[-1]), (s2)[-1]) : 0.f;     \
    float cmR = hasR ? fmaxf(fmaxf((s0)[8],  (s1)[8]),  (s2)[8])  : 0.f;     \
    float4 mA, mB;                                                           \
    mA.x = fmaxf(fmaxf(uA.x, cA.x), dA.x);                                   \
    mA.y = fmaxf(fmaxf(uA.y, cA.y), dA.y);                                   \
    mA.z = fmaxf(fmaxf(uA.z, cA.z), dA.z);                                   \
    mA.w = fmaxf(fmaxf(uA.w, cA.w), dA.w);                                   \
    mB.x = fmaxf(fmaxf(uB.x, cB.x), dB.x);                                   \
    mB.y = fmaxf(fmaxf(uB.y, cB.y), dB.y);                                   \
    mB.z = fmaxf(fmaxf(uB.z, cB.z), dB.z);                                   \
    mB.w = fmaxf(fmaxf(uB.w, cB.w), dB.w);                                   \
    float m0 = fmaxf(fmaxf(cmL,  mA.x), mA.y);                               \
    float m1 = fmaxf(fmaxf(mA.x, mA.y), mA.z);                               \
    float m2 = fmaxf(fmaxf(mA.y, mA.z), mA.w);                               \
    float m3 = fmaxf(fmaxf(mA.z, mA.w), mB.x);                               \
    float m4 = fmaxf(fmaxf(mA.w, mB.x), mB.y);                               \
    float m5 = fmaxf(fmaxf(mB.x, mB.y), mB.z);                               \
    float m6 = fmaxf(fmaxf(mB.y, mB.z), mB.w);                               \
    float m7 = fmaxf(fmaxf(mB.z, mB.w), cmR);                                \
    int _k = 0;                                                              \
    CAND_CHECK(p0, clA.x, cA.x, m0);                                         \
    CAND_CHECK(p1, clA.y, cA.y, m1);                                         \
    CAND_CHECK(p2, clA.z, cA.z, m2);                                         \
    CAND_CHECK(p3, clA.w, cA.w, m3);                                         \
    CAND_CHECK(p4, clB.x, cB.x, m4);                                         \
    CAND_CHECK(p5, clB.y, cB.y, m5);                                         \
    CAND_CHECK(p6, clB.z, cB.z, m6);                                         \
    CAND_CHECK(p7, clB.w, cB.w, m7);

template<int H, int W, int R, int LVL, int CAPL, int LOFF>
__device__ __forceinline__ void score_tile8(const float* __restrict__ cls,
                                            const float* __restrict__ gau,
                                            float* sg, int bid) {
    constexpr int hw  = H * W;
    constexpr int RPC = H / R;
    constexpr int w4  = W / 4;
    constexpr int NF4 = (R + 2) * w4;
    int tid = threadIdx.x;
    int cb  = bid / RPC;
    int ry  = (bid - cb * RPC) * R;
    int n   = cb / CCH;
    size_t base = (size_t)cb * hw;

    for (int i = tid; i < NF4; i += 256) {
        int row = i / w4;
        int c4  = i - row * w4;
        int gy  = min(max(ry - 1 + row, 0), H - 1);
        ((float4*)sg)[i] = *(const float4*)(gau + base + (size_t)gy * W + c4 * 4);
    }
    __syncthreads();

    int t  = tid * 8;
    int lr = t / W;
    int x0 = t - lr * W;
    int y  = ry + lr;
    int sr = lr + 1;

    const float* cp = cls + base + (size_t)y * W + x0;
    float4 clA = *(const float4*)cp;
    float4 clB = *(const float4*)(cp + 4);
    bool iy = (y > 0) & (y < H - 1);
    bool hasL = x0 > 0, hasR = x0 < W - 8;
    bool p0 = iy && hasL && (clA.x > BOX_LOGIT_THRESH);
    bool p1 = iy && (clA.y > BOX_LOGIT_THRESH);
    bool p2 = iy && (clA.z > BOX_LOGIT_THRESH);
    bool p3 = iy && (clA.w > BOX_LOGIT_THRESH);
    bool p4 = iy && (clB.x > BOX_LOGIT_THRESH);
    bool p5 = iy && (clB.y > BOX_LOGIT_THRESH);
    bool p6 = iy && (clB.z > BOX_LOGIT_THRESH);
    bool p7 = iy && hasR && (clB.w > BOX_LOGIT_THRESH);

    unsigned sbv[8]; int rrv[8]; int cnt = 0;
    int rb = (cb - n * CCH) * hw + y * W + x0;

    if (p0 | p1 | p2 | p3 | p4 | p5 | p6 | p7) {
        const float* s0 = sg + (sr - 1) * W + x0;
        const float* s1 = sg + sr * W + x0;
        const float* s2 = sg + (sr + 1) * W + x0;
        STENCIL8_BODY(s0, s1, s2)
    }
    emit8<LVL, CAPL, LOFF>(n, sbv, rrv, cnt);
}

template<int H, int W, int LVL, int CAPL, int LOFF>
__device__ __forceinline__ void score_body8(const float* __restrict__ cls,
                                            const float* __restrict__ gau, int bid) {
    constexpr int hw  = H * W;
    constexpr int CHW = CCH * hw;
    constexpr int OPI = CHW / 8;
    int q   = bid * 256 + threadIdx.x;
    int n   = q / OPI;
    int pix = q * 8;
    int r   = pix - n * CHW;
    int pp  = r % hw;
    int y   = pp / W;
    int x0  = pp & (W - 1);

    const float* cp = cls + (size_t)pix;
    float4 clA = *(const float4*)cp;
    float4 clB = *(const float4*)(cp + 4);
    bool iy = (y > 0) & (y < H - 1);
    bool hasL = x0 > 0, hasR = x0 < W - 8;
    bool p0 = iy && hasL && (clA.x > BOX_LOGIT_THRESH);
    bool p1 = iy && (clA.y > BOX_LOGIT_THRESH);
    bool p2 = iy && (clA.z > BOX_LOGIT_THRESH);
    bool p3 = iy && (clA.w > BOX_LOGIT_THRESH);
    bool p4 = iy && (clB.x > BOX_LOGIT_THRESH);
    bool p5 = iy && (clB.y > BOX_LOGIT_THRESH);
    bool p6 = iy && (clB.z > BOX_LOGIT_THRESH);
    bool p7 = iy && hasR && (clB.w > BOX_LOGIT_THRESH);

    unsigned sbv[8]; int rrv[8]; int cnt = 0;
    int rb = r;

    if (p0 | p1 | p2 | p3 | p4 | p5 | p6 | p7) {
        const float* Gb = gau + (size_t)(pix - pp);
        const float* s0 = Gb + pp - W;
        const float* s1 = Gb + pp;
        const float* s2 = Gb + pp + W;
        STENCIL8_BODY(s0, s1, s2)
    }
    emit8<LVL, CAPL, LOFF>(n, sbv, rrv, cnt);
}

__global__ void __launch_bounds__(256, 6) k_score_all(
    const float* __restrict__ c0, const float* __restrict__ g0,
    const float* __restrict__ c1, const float* __restrict__ g1,
    const float* __restrict__ c2, const float* __restrict__ g2) {
    __shared__ __align__(16) float sg[10 * 256];
    int bid = blockIdx.x;
    if (bid < 6400)       score_tile8<160,256,8, 0,CAP0,0>   (c0, g0, sg, bid);
    else if (bid < 8000)  score_tile8<80, 128,16,1,CAP1,CAP0>(c1, g1, sg, bid - 6400);
    else                  score_body8<40, 64, 2,CAP2,CAP0+CAP1>(c2, g2, bid - 8000);
}

// top-500 select per (image, level): smem 2-pass histogram + hybrid sort + fused solve
__global__ void __launch_bounds__(1024) k_select(const float* __restrict__ g0,
                                                 const float* __restrict__ g1,
                                                 const float* __restrict__ g2) {
    int b = blockIdx.x;
    int n = b / 3, lvl = b % 3;
    __shared__ unsigned int sh_c[1024];
    __shared__ unsigned int sh_f[256];
    __shared__ unsigned long long sel[4096];
    __shared__ unsigned int sT, sM, sAbove;
    __shared__ int sB;
    int tid = threadIdx.x;

    unsigned cnt = min(g_cnt[b], (unsigned)c_cap[lvl]);
    const unsigned long long* cand = &g_cand[(size_t)n * CAPI + c_loff[lvl]];
    const ulonglong2* cand2 = (const ulonglong2*)cand;
    unsigned half = cnt >> 1;
    bool odd = (cnt & 1u) != 0u;

    sh_c[tid] = 0;
    if (tid == 0) { sM = 0; sB = -1; sAbove = 0; sT = 0; }
    __syncthreads();
    if (tid == 0) g_cnt[b] = 0;   // safe: all threads read cnt before the barrier

    for (unsigned i = tid; i < half; i += 1024) {
        ulonglong2 kk = cand2[i];
        atomicAdd(&sh_c[(unsigned)(kk.x >> 32) >> 20], 1u);
        atomicAdd(&sh_c[(unsigned)(kk.y >> 32) >> 20], 1u);
    }
    if (tid == 0 && odd) atomicAdd(&sh_c[(unsigned)(cand[cnt - 1] >> 32) >> 20], 1u);
    __syncthreads();

    for (int off = 1; off < 1024; off <<= 1) {
        unsigned v = sh_c[tid];
        if (tid + off < 1024) v += sh_c[tid + off];
        __syncthreads();
        sh_c[tid] = v;
        __syncthreads();
    }
    if (sh_c[tid] >= TOPN && (tid == 1023 || sh_c[tid + 1] < TOPN)) {
        sB = tid;
        sAbove = (tid == 1023) ? 0u : sh_c[tid + 1];
    }
    if (tid < 256) sh_f[tid] = 0;
    __syncthreads();
    int B = sB;
    unsigned above = sAbove;

    if (B >= 0) {
        for (unsigned i = tid; i < half; i += 1024) {
            ulonglong2 kk = cand2[i];
            unsigned hx = (unsigned)(kk.x >> 32), hy = (unsigned)(kk.y >> 32);
            if ((int)(hx >> 20) == B) atomicAdd(&sh_f[(hx >> 12) & 255], 1u);
            if ((int)(hy >> 20) == B) atomicAdd(&sh_f[(hy >> 12) & 255], 1u);
        }
        if (tid == 0 && odd) {
            unsigned hz = (unsigned)(cand[cnt - 1] >> 32);
            if ((int)(hz >> 20) == B) atomicAdd(&sh_f[(hz >> 12) & 255], 1u);
        }
    }
    __syncthreads();
    for (int off = 1; off < 256; off <<= 1) {
        unsigned v = 0;
        if (tid < 256) { v = sh_f[tid]; if (tid + off < 256) v += sh_f[tid + off]; }
        __syncthreads();
        if (tid < 256) sh_f[tid] = v;
        __syncthreads();
    }
    if (B >= 0 && tid < 256) {
        unsigned cum = above + sh_f[tid];
        unsigned nxt = (tid == 255) ? above : above + sh_f[tid + 1];
        if (cum >= TOPN && nxt < TOPN) sT = ((unsigned)B << 8) | (unsigned)tid;
    }
    __syncthreads();
    unsigned T = sT;

    for (unsigned i = tid; i < half; i += 1024) {
        ulonglong2 kk = cand2[i];
        if ((unsigned)(kk.x >> 44) >= T) {
            unsigned p = atomicAdd(&sM, 1u);
            if (p < 4096) sel[p] = kk.x;
        }
        if ((unsigned)(kk.y >> 44) >= T) {
            unsigned p = atomicAdd(&sM, 1u);
            if (p < 4096) sel[p] = kk.y;
        }
    }
    if (tid == 0 && odd) {
        unsigned long long kz = cand[cnt - 1];
        if ((unsigned)(kz >> 44) >= T) {
            unsigned p = atomicAdd(&sM, 1u);
            if (p < 4096) sel[p] = kz;
        }
    }
    __syncthreads();
    unsigned mM = min(sM, 4096u);
    for (int i = tid; i < 4096; i += 1024)
        if ((unsigned)i >= mM) sel[i] = 0ull;
    __syncthreads();
    bitonic_desc_h<4096>(sel);

    if (tid < TOPN) {
        int t = n * NCAND + lvl * TOPN + tid;
        unsigned long long key = sel[tid];
        g_top[t] = key;

        int H, W, step; const float* G;
        if (lvl == 0)      { H = 160; W = 256; step = 8;  G = g0; }
        else if (lvl == 1) { H = 80;  W = 128; step = 16; G = g1; }
        else               { H = 40;  W = 64;  step = 32; G = g2; }
        float sc = __uint_as_float((unsigned)(key >> 32));
        unsigned flat = ~(unsigned)key;
        int hw = H * W;
        if (!(sc > 0.f) || flat >= (unsigned)(CCH * hw)) {
            g_x1[t]=0.f; g_y1[t]=0.f; g_x2[t]=0.f; g_y2[t]=0.f; g_lb[t]=1; g_vd[t]=0;
        } else {
            int c = (int)(flat / hw);
            int rem = (int)(flat - (unsigned)c * hw);
            int y = rem / W, x = rem - y * W;
            const float* Bp = G + ((size_t)(n * CCH + c)) * hw;
            auto LV = [&](int yy, int xx) -> float {
                yy = min(max(yy, 0), H - 1);
                xx = min(max(xx, 0), W - 1);
                return log1pf(expf(-Bp[yy * W + xx])) * 0.125f;
            };
            float l0 = LV(y, x);
            float lxp = LV(y, x+1), lxm = LV(y, x-1);
            float lyp = LV(y+1, x), lym = LV(y-1, x);
            float Ax = (lxp + lxm - 2.f * l0) * 0.5f;
            float Ay = (lyp + lym - 2.f * l0) * 0.5f;
            bool px = Ax > 1e-8f, py = Ay > 1e-8f;
            float Axs = px ? Ax : 1.f, Ays = py ? Ay : 1.f;
            float mux = (float)x - (lxp - lxm) / (4.f * Axs);
            float muy = (float)y - (lyp - lym) / (4.f * Ays);
            float wb = (px ? rsqrtf(2.f * Axs) : 0.f) * (float)step;
            float hb = (py ? rsqrtf(2.f * Ays) : 0.f) * (float)step;
            float x1 = mux * (float)step - 0.5f * wb + (float)(step - 1) * 0.5f;
            float y1 = muy * (float)step - 0.5f * hb + (float)(step - 1) * 0.5f;
            bool vd = (wb > 0.f) && (hb > 0.f);
            float x2 = x1 + wb - 1.f, y2 = y1 + hb - 1.f;
            g_x1[t] = fminf(fmaxf(x1, 0.f), 2047.f);
            g_x2[t] = fminf(fmaxf(x2, 0.f), 2047.f);
            g_y1[t] = fminf(fmaxf(y1, 0.f), 1279.f);
            g_y2[t] = fminf(fmaxf(y2, 0.f), 1279.f);
            g_lb[t] = c + 1; g_vd[t] = vd ? 1 : 0;
        }
    }
}

// per-image NMS: hybrid sort, then exact per-class greedy (one warp per class)
__global__ void __launch_bounds__(1024) k_nms(float* __restrict__ out) {
    __shared__ unsigned long long skey[2048];
    __shared__ float bx1[NCAND], by1[NCAND], bx2[NCAND], by2[NCAND];
    __shared__ short slb[NCAND];
    __shared__ unsigned char keep[NCAND];
    __shared__ short cls_list[NCAND];
    __shared__ int   ofs[82];
    __shared__ int   s_ti[100];
    int n = blockIdx.x, tid = threadIdx.x;
    int w = tid >> 5, lane = tid & 31;

    for (int p = tid; p < 2048; p += 1024) {
        unsigned long long kk = 0ull;
        if (p < NCAND) {
            int gi = n * NCAND + p;
            float sc = __uint_as_float((unsigned)(g_top[gi] >> 32));
            float sv = g_vd[gi] ? sc : -1.f;
            unsigned bits = __float_as_uint(sv);
            unsigned ord = (bits & 0x80000000u) ? ~bits : (bits | 0x80000000u);
            kk = ((unsigned long long)ord << 32) | (0xFFFFFFFFu - (unsigned)p);
        }
        skey[p] = kk;
    }
    __syncthreads();
    bitonic_desc_h<2048>(skey);

    for (int p = tid; p < NCAND; p += 1024) {
        int pos = (int)(0xFFFFFFFFu - (unsigned)skey[p]);
        int gi = n * NCAND + pos;
        bx1[p]=g_x1[gi]; by1[p]=g_y1[gi]; bx2[p]=g_x2[gi]; by2[p]=g_y2[gi];
        slb[p]=(short)g_lb[gi]; keep[p]=g_vd[gi];
    }
    if (tid < 82) ofs[tid] = 0;
    __syncthreads();

    for (int p = tid; p < NCAND; p += 1024)
        if (keep[p]) atomicAdd((unsigned*)&ofs[slb[p]], 1u);
    __syncthreads();
    if (tid == 0) {
        int acc = 0;
        for (int c = 1; c <= 80; c++) { int v = ofs[c]; ofs[c] = acc; acc += v; }
        ofs[81] = acc;
        ofs[0]  = 0;
    }
    __syncthreads();

    for (int lbl = w + 1; lbl <= 80; lbl += 32) {
        int start = ofs[lbl];
        int fill = 0;
        for (int base = 0; base < NCAND; base += 32) {
            int p = base + lane;
            bool match = (p < NCAND) && keep[p] && (slb[p] == (short)lbl);
            unsigned bal = __ballot_sync(0xFFFFFFFFu, match);
            if (match) {
                int pre = __popc(bal & ((1u << lane) - 1u));
                cls_list[start + fill + pre] = (short)p;
            }
            fill += __popc(bal);
        }
    }
    __syncthreads();

    for (int lbl = w + 1; lbl <= 80; lbl += 32) {
        int start = ofs[lbl];
        int k = ofs[lbl + 1] - start;
        if (k < 2) continue;
        for (int t0 = 0; t0 < k; t0 += 32) {
            int e = t0 + lane;
            bool in = e < k;
            int idx = in ? (int)cls_list[start + e] : 0;
            float x1 = 0, y1 = 0, x2 = 0, y2 = 0, ar = 1.f;
            bool alive = false;
            if (in) {
                x1 = bx1[idx]; y1 = by1[idx]; x2 = bx2[idx]; y2 = by2[idx];
                ar = (x2 - x1 + 1.f) * (y2 - y1 + 1.f);
                alive = keep[idx] != 0;
            }
            if (alive) {
                for (int qe = 0; qe < t0; qe++) {
                    int qi = (int)cls_list[start + qe];
                    if (!keep[qi]) continue;
                    float qx1 = bx1[qi], qy1 = by1[qi], qx2 = bx2[qi], qy2 = by2[qi];
                    float iw = fmaxf(fminf(x2, qx2) - fmaxf(x1, qx1) + 1.f, 0.f);
                    float ih = fmaxf(fminf(y2, qy2) - fmaxf(y1, qy1) + 1.f, 0.f);
                    float inter = iw * ih;
                    float qar = (qx2 - qx1 + 1.f) * (qy2 - qy1 + 1.f);
                    if (inter / (ar + qar - inter + 1e-9f) > 0.5f) { alive = false; break; }
                }
            }
            int lim = min(32, k - t0);
            unsigned sup = 0;
            for (int m = 0; m < lim - 1; m++) {
                float mx1 = __shfl_sync(0xFFFFFFFFu, x1, m);
                float my1 = __shfl_sync(0xFFFFFFFFu, y1, m);
                float mx2 = __shfl_sync(0xFFFFFFFFu, x2, m);
                float my2 = __shfl_sync(0xFFFFFFFFu, y2, m);
                float mar = __shfl_sync(0xFFFFFFFFu, ar, m);
                if (in && m < lane) {
                    float iw = fmaxf(fminf(x2, mx2) - fmaxf(x1, mx1) + 1.f, 0.f);
                    float ih = fmaxf(fminf(y2, my2) - fmaxf(y1, my1) + 1.f, 0.f);
                    float inter = iw * ih;
                    if (inter / (ar + mar - inter + 1e-9f) > 0.5f) sup |= (1u << m);
                }
            }
            for (int m = 0; m < lim - 1; m++) {
                unsigned bal = __ballot_sync(0xFFFFFFFFu, alive);
                if (lane > m && ((bal >> m) & 1u) && ((sup >> m) & 1u)) alive = false;
            }
            if (in) keep[idx] = alive ? 1 : 0;
        }
    }
    __syncthreads();

    if (tid < 32) {
        int cnt = 0;
        for (int pass = 0; pass < 2; pass++) {
            for (int b2 = 0; b2 < NCAND && cnt < 100; b2 += 32) {
                int i2 = b2 + lane;
                bool pr = (i2 < NCAND) && ((pass == 0) ? (keep[i2] != 0) : (keep[i2] == 0));
                unsigned ww = __ballot_sync(0xFFFFFFFFu, pr);
                int pre = __popc(ww & ((1u << lane) - 1u));
                if (pr && cnt + pre < 100) s_ti[cnt + pre] = i2;
                cnt += __popc(ww);
            }
            if (cnt > 100) cnt = 100;
        }
    }
    __syncthreads();

    if (tid < 100) {
        int p = s_ti[tid];
        unsigned ord = (unsigned)(skey[p] >> 32);
        float s = (ord & 0x80000000u) ? __uint_as_float(ord ^ 0x80000000u)
                                      : __uint_as_float(~ord);
        float tv = keep[p] ? s : -1.f;
        out[n*400 + tid*4 + 0] = bx1[p];
        out[n*400 + tid*4 + 1] = by1[p];
        out[n*400 + tid*4 + 2] = bx2[p];
        out[n*400 + tid*4 + 3] = by2[p];
        out[1600 + n*100 + tid] = tv;
        out[2000 + n*100 + tid] = (float)slb[p];
        out[2400 + n*100 + tid] = (tv > 0.f) ? 1.f : 0.f;
    }
}

extern "C" void kernel_launch(void* const* d_in, const int* in_sizes, int n_in,
                              void* d_out, int out_size) {
    const float *cls[3], *gau[3];
    if (in_sizes[0] == in_sizes[1]) {          // interleaved
        cls[0]=(const float*)d_in[0]; gau[0]=(const float*)d_in[1];
        cls[1]=(const float*)d_in[2]; gau[1]=(const float*)d_in[3];
        cls[2]=(const float*)d_in[4]; gau[2]=(const float*)d_in[5];
    } else {                                   // grouped
        cls[0]=(const float*)d_in[0]; cls[1]=(const float*)d_in[1]; cls[2]=(const float*)d_in[2];
        gau[0]=(const float*)d_in[3]; gau[1]=(const float*)d_in[4]; gau[2]=(const float*)d_in[5];
    }
    float* out = (float*)d_out;

    k_score_all<<<8400, 256>>>(cls[0], gau[0], cls[1], gau[1], cls[2], gau[2]);
    k_select<<<NIMG * 3, 1024>>>(gau[0], gau[1], gau[2]);
    k_nms<<<NIMG, 1024>>>(out);
}

// round 15
// speedup vs baseline: 1.1920x; 1.0519x over previous
#include <cuda_runtime.h>
#include <cstdint>

#define NIMG  4
#define CCH   80
#define TOPN  500
#define NCAND 1500
#define CAP0 524288
#define CAP1 131072
#define CAP2 65536
#define CAPI (CAP0+CAP1+CAP2)
#define NSLICE 16
#define NBIN2 8192
#define BOX_LOGIT_THRESH (-2.9444389791664403f)

__device__ __align__(16) unsigned long long g_cand[NIMG * CAPI];
__device__ unsigned int       g_cnt[NIMG * 3];
__device__ unsigned int       g_hist2[NIMG * 3 * NBIN2];
__device__ __align__(16) unsigned long long g_selbuf[NIMG * 3 * 4096];
__device__ unsigned int       g_selcnt[NIMG * 3];
__device__ unsigned int       g_T8[NIMG * 3];
__device__ unsigned long long g_top[NIMG * NCAND];
__device__ float g_x1[NIMG*NCAND], g_y1[NIMG*NCAND], g_x2[NIMG*NCAND], g_y2[NIMG*NCAND];
__device__ int   g_lb[NIMG*NCAND];
__device__ unsigned char g_vd[NIMG*NCAND];

__constant__ int c_cap[3]  = {CAP0, CAP1, CAP2};
__constant__ int c_loff[3] = {0, CAP0, CAP0 + CAP1};

__device__ __forceinline__ float sigm(float x) {
    if (x >= 0.f) return 1.f / (1.f + expf(-x));
    float e = expf(x); return e / (1.f + e);
}

// hybrid bitonic descending sort, SZ elements, 1024 threads.
template<int SZ>
__device__ void bitonic_desc_h(unsigned long long* a) {
    constexpr int E = SZ / 1024;
    int tid = threadIdx.x;
    unsigned long long v[E];
    #pragma unroll
    for (int m = 0; m < E; m++) v[m] = a[tid + (m << 10)];
    #pragma unroll
    for (int k = 2; k <= 32; k <<= 1) {
        #pragma unroll
        for (int j = k >> 1; j >= 1; j >>= 1) {
            #pragma unroll
            for (int m = 0; m < E; m++) {
                int t = tid + (m << 10);
                unsigned long long pv = __shfl_xor_sync(0xFFFFFFFFu, v[m], j);
                bool keepmax = (((t & k) == 0) == ((t & j) == 0));
                if (keepmax == (pv > v[m])) v[m] = pv;
            }
        }
    }
    #pragma unroll
    for (int m = 0; m < E; m++) a[tid + (m << 10)] = v[m];
    __syncthreads();
    for (int k = 64; k <= SZ; k <<= 1) {
        for (int j = k >> 1; j >= 32; j >>= 1) {
            #pragma unroll
            for (int m = 0; m < E; m++) {
                int t = tid + (m << 10);
                int ixj = t ^ j;
                if (ixj > t) {
                    unsigned long long u = a[t], w = a[ixj];
                    bool sw = ((t & k) == 0) ? (u < w) : (u > w);
                    if (sw) { a[t] = w; a[ixj] = u; }
                }
            }
            __syncthreads();
        }
        #pragma unroll
        for (int m = 0; m < E; m++) v[m] = a[tid + (m << 10)];
        #pragma unroll
        for (int j = 16; j >= 1; j >>= 1) {
            #pragma unroll
            for (int m = 0; m < E; m++) {
                int t = tid + (m << 10);
                unsigned long long pv = __shfl_xor_sync(0xFFFFFFFFu, v[m], j);
                bool keepmax = (((t & k) == 0) == ((t & j) == 0));
                if (keepmax == (pv > v[m])) v[m] = pv;
            }
        }
        #pragma unroll
        for (int m = 0; m < E; m++) a[tid + (m << 10)] = v[m];
        __syncthreads();
    }
}

// warp-aggregated candidate emit (up to 8 per thread)
template<int LVL, int CAPL, int LOFF>
__device__ __forceinline__ void emit8(int n, const unsigned* sbv, const int* rrv, int cnt) {
    int lane = threadIdx.x & 31;
    unsigned cinc = (unsigned)cnt;
    #pragma unroll
    for (int off = 1; off < 32; off <<= 1) {
        unsigned t = __shfl_up_sync(0xFFFFFFFFu, cinc, off);
        if (lane >= off) cinc += t;
    }
    unsigned total = __shfl_sync(0xFFFFFFFFu, cinc, 31);
    if (total == 0u) return;
    int b = n * 3 + LVL;
    unsigned base = 0;
    if (lane == 0) base = atomicAdd(&g_cnt[b], total);
    base = __shfl_sync(0xFFFFFFFFu, base, 0);
    unsigned pre = cinc - (unsigned)cnt;
    #pragma unroll
    for (int k = 0; k < 8; k++) {
        if (k >= cnt) break;
        unsigned slot = base + pre + (unsigned)k;
        if (slot < (unsigned)CAPL)
            g_cand[(size_t)n * CAPI + LOFF + slot] =
                ((unsigned long long)sbv[k] << 32) | (unsigned)(~rrv[k]);
    }
}

#define CAND_CHECK(px, cl, gc, m) do {                                       \
    if ((px) && ((gc) >= (m))) {                                             \
        float sc_ = sqrtf(sigm(cl) * sigm(gc));                              \
        sbv[cnt] = __float_as_uint(sc_); rrv[cnt] = rb + _k; cnt++;          \
    } _k++;                                                                  \
} while (0)

#define STENCIL8_BODY(s0, s1, s2)                                            \
    float4 uA = *(const float4*)(s0), uB = *(const float4*)((s0) + 4);       \
    float4 cA = *(const float4*)(s1), cB = *(const float4*)((s1) + 4);       \
    float4 dA = *(const float4*)(s2), dB = *(const float4*)((s2) + 4);       \
    float cmL = hasL ? fmaxf(fmaxf((s0)[-1], (s1)[-1]), (s2)[-1]) : 0.f;     \
    float cmR = hasR ? fmaxf(fmaxf((s0)[8],  (s1)[8]),  (s2)[8])  : 0.f;     \
    float4 mA, mB;                                                           \
    mA.x = fmaxf(fmaxf(uA.x, cA.x), dA.x);                                   \
    mA.y = fmaxf(fmaxf(uA.y, cA.y), dA.y);                                   \
    mA.z = fmaxf(fmaxf(uA.z, cA.z), dA.z);                                   \
    mA.w = fmaxf(fmaxf(uA.w, cA.w), dA.w);                                   \
    mB.x = fmaxf(fmaxf(uB.x, cB.x), dB.x);                                   \
    mB.y = fmaxf(fmaxf(uB.y, cB.y), dB.y);                                   \
    mB.z = fmaxf(fmaxf(uB.z, cB.z), dB.z);                                   \
    mB.w = fmaxf(fmaxf(uB.w, cB.w), dB.w);                                   \
    float m0 = fmaxf(fmaxf(cmL,  mA.x), mA.y);                               \
    float m1 = fmaxf(fmaxf(mA.x, mA.y), mA.z);                               \
    float m2 = fmaxf(fmaxf(mA.y, mA.z), mA.w);                               \
    float m3 = fmaxf(fmaxf(mA.z, mA.w), mB.x);                               \
    float m4 = fmaxf(fmaxf(mA.w, mB.x), mB.y);                               \
    float m5 = fmaxf(fmaxf(mB.x, mB.y), mB.z);                               \
    float m6 = fmaxf(fmaxf(mB.y, mB.z), mB.w);                               \
    float m7 = fmaxf(fmaxf(mB.z, mB.w), cmR);                                \
    int _k = 0;                                                              \
    CAND_CHECK(p0, clA.x, cA.x, m0);                                         \
    CAND_CHECK(p1, clA.y, cA.y, m1);                                         \
    CAND_CHECK(p2, clA.z, cA.z, m2);                                         \
    CAND_CHECK(p3, clA.w, cA.w, m3);                                         \
    CAND_CHECK(p4, clB.x, cB.x, m4);                                         \
    CAND_CHECK(p5, clB.y, cB.y, m5);                                         \
    CAND_CHECK(p6, clB.z, cB.z, m6);                                         \
    CAND_CHECK(p7, clB.w, cB.w, m7);

template<int H, int W, int R, int LVL, int CAPL, int LOFF>
__device__ __forceinline__ void score_tile8(const float* __restrict__ cls,
                                            const float* __restrict__ gau,
                                            float* sg, int bid) {
    constexpr int hw  = H * W;
    constexpr int RPC = H / R;
    constexpr int w4  = W / 4;
    constexpr int NF4 = (R + 2) * w4;
    int tid = threadIdx.x;
    int cb  = bid / RPC;
    int ry  = (bid - cb * RPC) * R;
    int n   = cb / CCH;
    size_t base = (size_t)cb * hw;

    for (int i = tid; i < NF4; i += 256) {
        int row = i / w4;
        int c4  = i - row * w4;
        int gy  = min(max(ry - 1 + row, 0), H - 1);
        ((float4*)sg)[i] = *(const float4*)(gau + base + (size_t)gy * W + c4 * 4);
    }
    __syncthreads();

    int t  = tid * 8;
    int lr = t / W;
    int x0 = t - lr * W;
    int y  = ry + lr;
    int sr = lr + 1;

    const float* cp = cls + base + (size_t)y * W + x0;
    float4 clA = *(const float4*)cp;
    float4 clB = *(const float4*)(cp + 4);
    bool iy = (y > 0) & (y < H - 1);
    bool hasL = x0 > 0, hasR = x0 < W - 8;
    bool p0 = iy && hasL && (clA.x > BOX_LOGIT_THRESH);
    bool p1 = iy && (clA.y > BOX_LOGIT_THRESH);
    bool p2 = iy && (clA.z > BOX_LOGIT_THRESH);
    bool p3 = iy && (clA.w > BOX_LOGIT_THRESH);
    bool p4 = iy && (clB.x > BOX_LOGIT_THRESH);
    bool p5 = iy && (clB.y > BOX_LOGIT_THRESH);
    bool p6 = iy && (clB.z > BOX_LOGIT_THRESH);
    bool p7 = iy && hasR && (clB.w > BOX_LOGIT_THRESH);

    unsigned sbv[8]; int rrv[8]; int cnt = 0;
    int rb = (cb - n * CCH) * hw + y * W + x0;

    if (p0 | p1 | p2 | p3 | p4 | p5 | p6 | p7) {
        const float* s0 = sg + (sr - 1) * W + x0;
        const float* s1 = sg + sr * W + x0;
        const float* s2 = sg + (sr + 1) * W + x0;
        STENCIL8_BODY(s0, s1, s2)
    }
    emit8<LVL, CAPL, LOFF>(n, sbv, rrv, cnt);
}

template<int H, int W, int LVL, int CAPL, int LOFF>
__device__ __forceinline__ void score_body8(const float* __restrict__ cls,
                                            const float* __restrict__ gau, int bid) {
    constexpr int hw  = H * W;
    constexpr int CHW = CCH * hw;
    constexpr int OPI = CHW / 8;
    int q   = bid * 256 + threadIdx.x;
    int n   = q / OPI;
    int pix = q * 8;
    int r   = pix - n * CHW;
    int pp  = r % hw;
    int y   = pp / W;
    int x0  = pp & (W - 1);

    const float* cp = cls + (size_t)pix;
    float4 clA = *(const float4*)cp;
    float4 clB = *(const float4*)(cp + 4);
    bool iy = (y > 0) & (y < H - 1);
    bool hasL = x0 > 0, hasR = x0 < W - 8;
    bool p0 = iy && hasL && (clA.x > BOX_LOGIT_THRESH);
    bool p1 = iy && (clA.y > BOX_LOGIT_THRESH);
    bool p2 = iy && (clA.z > BOX_LOGIT_THRESH);
    bool p3 = iy && (clA.w > BOX_LOGIT_THRESH);
    bool p4 = iy && (clB.x > BOX_LOGIT_THRESH);
    bool p5 = iy && (clB.y > BOX_LOGIT_THRESH);
    bool p6 = iy && (clB.z > BOX_LOGIT_THRESH);
    bool p7 = iy && hasR && (clB.w > BOX_LOGIT_THRESH);

    unsigned sbv[8]; int rrv[8]; int cnt = 0;
    int rb = r;

    if (p0 | p1 | p2 | p3 | p4 | p5 | p6 | p7) {
        const float* Gb = gau + (size_t)(pix - pp);
        const float* s0 = Gb + pp - W;
        const float* s1 = Gb + pp;
        const float* s2 = Gb + pp + W;
        STENCIL8_BODY(s0, s1, s2)
    }
    emit8<LVL, CAPL, LOFF>(n, sbv, rrv, cnt);
}

__global__ void __launch_bounds__(256, 6) k_score_all(
    const float* __restrict__ c0, const float* __restrict__ g0,
    const float* __restrict__ c1, const float* __restrict__ g1,
    const float* __restrict__ c2, const float* __restrict__ g2) {
    __shared__ __align__(16) float sg[10 * 256];
    int bid = blockIdx.x;
    if (bid < 6400)       score_tile8<160,256,8, 0,CAP0,0>   (c0, g0, sg, bid);
    else if (bid < 8000)  score_tile8<80, 128,16,1,CAP1,CAP0>(c1, g1, sg, bid - 6400);
    else                  score_body8<40, 64, 2,CAP2,CAP0+CAP1>(c2, g2, bid - 8000);
}

// phase A: slice-parallel coarse histogram (sb>>17, 8192 bins)
__global__ void __launch_bounds__(256) k_histA() {
    int blk = blockIdx.x;
    int b = blk >> 4, s = blk & (NSLICE - 1);
    int lvl = b % 3, n = b / 3;
    __shared__ unsigned int h[NBIN2];
    for (int i = threadIdx.x; i < NBIN2; i += 256) h[i] = 0;
    __syncthreads();
    unsigned cnt = min(g_cnt[b], (unsigned)c_cap[lvl]);
    const unsigned long long* cand = &g_cand[(size_t)n * CAPI + c_loff[lvl]];
    unsigned lo = (unsigned)(((unsigned long long)s * cnt) >> 4);
    unsigned hi = (unsigned)(((unsigned long long)(s + 1) * cnt) >> 4);
    for (unsigned i = lo + threadIdx.x; i < hi; i += 256)
        atomicAdd(&h[(unsigned)(cand[i] >> 49)], 1u);
    __syncthreads();
    for (int i = threadIdx.x; i < NBIN2; i += 256)
        if (h[i]) atomicAdd(&g_hist2[(size_t)b * NBIN2 + i], h[i]);
}

// phase B: per-(n,lvl) threshold bin from suffix sums; zeroes hist + selcnt
__global__ void __launch_bounds__(1024) k_thresh() {
    int b = blockIdx.x;
    __shared__ unsigned int bh[NBIN2];
    __shared__ unsigned int tot[1024];
    int tid = threadIdx.x;
    unsigned int* H = &g_hist2[(size_t)b * NBIN2];
    unsigned v[8];
    #pragma unroll
    for (int m = 0; m < 8; m++) v[m] = H[tid * 8 + m];
    #pragma unroll
    for (int m = 0; m < 8; m++) H[tid * 8 + m] = 0;   // ready for next replay
    unsigned acc = 0;
    #pragma unroll
    for (int m = 7; m >= 0; m--) { acc += v[m]; v[m] = acc; }
    tot[tid] = acc;
    if (tid == 0) { g_T8[b] = 0; g_selcnt[b] = 0; }
    __syncthreads();
    for (int off = 1; off < 1024; off <<= 1) {
        unsigned t = tot[tid];
        if (tid + off < 1024) t += tot[tid + off];
        __syncthreads();
        tot[tid] = t;
        __syncthreads();
    }
    unsigned later = (tid == 1023) ? 0u : tot[tid + 1];
    #pragma unroll
    for (int m = 0; m < 8; m++) bh[tid * 8 + m] = v[m] + later;
    __syncthreads();
    #pragma unroll
    for (int m = 0; m < 8; m++) {
        int i = tid * 8 + m;
        unsigned si = bh[i];
        unsigned sn = (i == NBIN2 - 1) ? 0u : bh[i + 1];
        if (si >= (unsigned)TOPN && sn < (unsigned)TOPN) g_T8[b] = (unsigned)i;
    }
}

// phase C: slice-parallel collect of keys >= threshold (warp-aggregated append)
__global__ void __launch_bounds__(256) k_collect() {
    int blk = blockIdx.x;
    int b = blk >> 4, s = blk & (NSLICE - 1);
    int lvl = b % 3, n = b / 3;
    unsigned cnt = min(g_cnt[b], (unsigned)c_cap[lvl]);
    unsigned T8 = g_T8[b];
    const unsigned long long* cand = &g_cand[(size_t)n * CAPI + c_loff[lvl]];
    unsigned lo = (unsigned)(((unsigned long long)s * cnt) >> 4);
    unsigned hi = (unsigned)(((unsigned long long)(s + 1) * cnt) >> 4);
    int lane = threadIdx.x & 31;
    for (unsigned i = lo + threadIdx.x; ; i += 256) {
        bool in = i < hi;
        unsigned long long k = in ? cand[i] : 0ull;
        bool take = in && ((unsigned)(k >> 49) >= T8);
        unsigned bal = __ballot_sync(0xFFFFFFFFu, take);
        if (__ballot_sync(0xFFFFFFFFu, in) == 0u) break;
        if (bal) {
            int lead = __ffs(bal) - 1;
            unsigned base = 0;
            if (lane == lead) base = atomicAdd(&g_selcnt[b], (unsigned)__popc(bal));
            base = __shfl_sync(0xFFFFFFFFu, base, lead);
            if (take) {
                unsigned slot = base + (unsigned)__popc(bal & ((1u << lane) - 1u));
                if (slot < 4096u) g_selbuf[(size_t)b * 4096 + slot] = k;
            }
        }
    }
}

// phase D: sort collected keys, emit top-500 + fused box solve; resets g_cnt
__global__ void __launch_bounds__(1024) k_final(const float* __restrict__ g0,
                                                const float* __restrict__ g1,
                                                const float* __restrict__ g2) {
    int b = blockIdx.x;
    int n = b / 3, lvl = b % 3;
    __shared__ unsigned long long sel[4096];
    int tid = threadIdx.x;
    unsigned mN = min(g_selcnt[b], 4096u);
    if (tid == 0) g_cnt[b] = 0;   // reset for next graph replay
    const unsigned long long* sb_ = &g_selbuf[(size_t)b * 4096];
    for (int i = tid; i < 4096; i += 1024)
        sel[i] = ((unsigned)i < mN) ? sb_[i] : 0ull;
    __syncthreads();
    bitonic_desc_h<4096>(sel);

    if (tid < TOPN) {
        int t = n * NCAND + lvl * TOPN + tid;
        unsigned long long key = sel[tid];
        g_top[t] = key;

        int H, W, step; const float* G;
        if (lvl == 0)      { H = 160; W = 256; step = 8;  G = g0; }
        else if (lvl == 1) { H = 80;  W = 128; step = 16; G = g1; }
        else               { H = 40;  W = 64;  step = 32; G = g2; }
        float sc = __uint_as_float((unsigned)(key >> 32));
        unsigned flat = ~(unsigned)key;
        int hw = H * W;
        if (!(sc > 0.f) || flat >= (unsigned)(CCH * hw)) {
            g_x1[t]=0.f; g_y1[t]=0.f; g_x2[t]=0.f; g_y2[t]=0.f; g_lb[t]=1; g_vd[t]=0;
        } else {
            int c = (int)(flat / hw);
            int rem = (int)(flat - (unsigned)c * hw);
            int y = rem / W, x = rem - y * W;
            const float* Bp = G + ((size_t)(n * CCH + c)) * hw;
            auto LV = [&](int yy, int xx) -> float {
                yy = min(max(yy, 0), H - 1);
                xx = min(max(xx, 0), W - 1);
                return log1pf(expf(-Bp[yy * W + xx])) * 0.125f;
            };
            float l0 = LV(y, x);
            float lxp = LV(y, x+1), lxm = LV(y, x-1);
            float lyp = LV(y+1, x), lym = LV(y-1, x);
            float Ax = (lxp + lxm - 2.f * l0) * 0.5f;
            float Ay = (lyp + lym - 2.f * l0) * 0.5f;
            bool px = Ax > 1e-8f, py = Ay > 1e-8f;
            float Axs = px ? Ax : 1.f, Ays = py ? Ay : 1.f;
            float mux = (float)x - (lxp - lxm) / (4.f * Axs);
            float muy = (float)y - (lyp - lym) / (4.f * Ays);
            float wb = (px ? rsqrtf(2.f * Axs) : 0.f) * (float)step;
            float hb = (py ? rsqrtf(2.f * Ays) : 0.f) * (float)step;
            float x1 = mux * (float)step - 0.5f * wb + (float)(step - 1) * 0.5f;
            float y1 = muy * (float)step - 0.5f * hb + (float)(step - 1) * 0.5f;
            bool vd = (wb > 0.f) && (hb > 0.f);
            float x2 = x1 + wb - 1.f, y2 = y1 + hb - 1.f;
            g_x1[t] = fminf(fmaxf(x1, 0.f), 2047.f);
            g_x2[t] = fminf(fmaxf(x2, 0.f), 2047.f);
            g_y1[t] = fminf(fmaxf(y1, 0.f), 1279.f);
            g_y2[t] = fminf(fmaxf(y2, 0.f), 1279.f);
            g_lb[t] = c + 1; g_vd[t] = vd ? 1 : 0;
        }
    }
}

// per-image NMS: hybrid sort, then exact per-class greedy (one warp per class)
__global__ void __launch_bounds__(1024) k_nms(float* __restrict__ out) {
    __shared__ unsigned long long skey[2048];
    __shared__ float bx1[NCAND], by1[NCAND], bx2[NCAND], by2[NCAND];
    __shared__ short slb[NCAND];
    __shared__ unsigned char keep[NCAND];
    __shared__ short cls_list[NCAND];
    __shared__ int   ofs[82];
    __shared__ int   s_ti[100];
    int n = blockIdx.x, tid = threadIdx.x;
    int w = tid >> 5, lane = tid & 31;

    for (int p = tid; p < 2048; p += 1024) {
        unsigned long long kk = 0ull;
        if (p < NCAND) {
            int gi = n * NCAND + p;
            float sc = __uint_as_float((unsigned)(g_top[gi] >> 32));
            float sv = g_vd[gi] ? sc : -1.f;
            unsigned bits = __float_as_uint(sv);
            unsigned ord = (bits & 0x80000000u) ? ~bits : (bits | 0x80000000u);
            kk = ((unsigned long long)ord << 32) | (0xFFFFFFFFu - (unsigned)p);
        }
        skey[p] = kk;
    }
    __syncthreads();
    bitonic_desc_h<2048>(skey);

    for (int p = tid; p < NCAND; p += 1024) {
        int pos = (int)(0xFFFFFFFFu - (unsigned)skey[p]);
        int gi = n * NCAND + pos;
        bx1[p]=g_x1[gi]; by1[p]=g_y1[gi]; bx2[p]=g_x2[gi]; by2[p]=g_y2[gi];
        slb[p]=(short)g_lb[gi]; keep[p]=g_vd[gi];
    }
    if (tid < 82) ofs[tid] = 0;
    __syncthreads();

    for (int p = tid; p < NCAND; p += 1024)
        if (keep[p]) atomicAdd((unsigned*)&ofs[slb[p]], 1u);
    __syncthreads();
    if (tid == 0) {
        int acc = 0;
        for (int c = 1; c <= 80; c++) { int v = ofs[c]; ofs[c] = acc; acc += v; }
        ofs[81] = acc;
        ofs[0]  = 0;
    }
    __syncthreads();

    for (int lbl = w + 1; lbl <= 80; lbl += 32) {
        int start = ofs[lbl];
        int fill = 0;
        for (int base = 0; base < NCAND; base += 32) {
            int p = base + lane;
            bool match = (p < NCAND) && keep[p] && (slb[p] == (short)lbl);
            unsigned bal = __ballot_sync(0xFFFFFFFFu, match);
            if (match) {
                int pre = __popc(bal & ((1u << lane) - 1u));
                cls_list[start + fill + pre] = (short)p;
            }
            fill += __popc(bal);
        }
    }
    __syncthreads();

    for (int lbl = w + 1; lbl <= 80; lbl += 32) {
        int start = ofs[lbl];
        int k = ofs[lbl + 1] - start;
        if (k < 2) continue;
        for (int t0 = 0; t0 < k; t0 += 32) {
            int e = t0 + lane;
            bool in = e < k;
            int idx = in ? (int)cls_list[start + e] : 0;
            float x1 = 0, y1 = 0, x2 = 0, y2 = 0, ar = 1.f;
            bool alive = false;
            if (in) {
                x1 = bx1[idx]; y1 = by1[idx]; x2 = bx2[idx]; y2 = by2[idx];
                ar = (x2 - x1 + 1.f) * (y2 - y1 + 1.f);
                alive = keep[idx] != 0;
            }
            if (alive) {
                for (int qe = 0; qe < t0; qe++) {
                    int qi = (int)cls_list[start + qe];
                    if (!keep[qi]) continue;
                    float qx1 = bx1[qi], qy1 = by1[qi], qx2 = bx2[qi], qy2 = by2[qi];
                    float iw = fmaxf(fminf(x2, qx2) - fmaxf(x1, qx1) + 1.f, 0.f);
                    float ih = fmaxf(fminf(y2, qy2) - fmaxf(y1, qy1) + 1.f, 0.f);
                    float inter = iw * ih;
                    float qar = (qx2 - qx1 + 1.f) * (qy2 - qy1 + 1.f);
                    if (inter / (ar + qar - inter + 1e-9f) > 0.5f) { alive = false; break; }
                }
            }
            int lim = min(32, k - t0);
            unsigned sup = 0;
            for (int m = 0; m < lim - 1; m++) {
                float mx1 = __shfl_sync(0xFFFFFFFFu, x1, m);
                float my1 = __shfl_sync(0xFFFFFFFFu, y1, m);
                float mx2 = __shfl_sync(0xFFFFFFFFu, x2, m);
                float my2 = __shfl_sync(0xFFFFFFFFu, y2, m);
                float mar = __shfl_sync(0xFFFFFFFFu, ar, m);
                if (in && m < lane) {
                    float iw = fmaxf(fminf(x2, mx2) - fmaxf(x1, mx1) + 1.f, 0.f);
                    float ih = fmaxf(fminf(y2, my2) - fmaxf(y1, my1) + 1.f, 0.f);
                    float inter = iw * ih;
                    if (inter / (ar + mar - inter + 1e-9f) > 0.5f) sup |= (1u << m);
                }
            }
            for (int m = 0; m < lim - 1; m++) {
                unsigned bal = __ballot_sync(0xFFFFFFFFu, alive);
                if (lane > m && ((bal >> m) & 1u) && ((sup >> m) & 1u)) alive = false;
            }
            if (in) keep[idx] = alive ? 1 : 0;
        }
    }
    __syncthreads();

    if (tid < 32) {
        int cnt = 0;
        for (int pass = 0; pass < 2; pass++) {
            for (int b2 = 0; b2 < NCAND && cnt < 100; b2 += 32) {
                int i2 = b2 + lane;
                bool pr = (i2 < NCAND) && ((pass == 0) ? (keep[i2] != 0) : (keep[i2] == 0));
                unsigned ww = __ballot_sync(0xFFFFFFFFu, pr);
                int pre = __popc(ww & ((1u << lane) - 1u));
                if (pr && cnt + pre < 100) s_ti[cnt + pre] = i2;
                cnt += __popc(ww);
            }
            if (cnt > 100) cnt = 100;
        }
    }
    __syncthreads();

    if (tid < 100) {
        int p = s_ti[tid];
        unsigned ord = (unsigned)(skey[p] >> 32);
        float s = (ord & 0x80000000u) ? __uint_as_float(ord ^ 0x80000000u)
                                      : __uint_as_float(~ord);
        float tv = keep[p] ? s : -1.f;
        out[n*400 + tid*4 + 0] = bx1[p];
        out[n*400 + tid*4 + 1] = by1[p];
        out[n*400 + tid*4 + 2] = bx2[p];
        out[n*400 + tid*4 + 3] = by2[p];
        out[1600 + n*100 + tid] = tv;
        out[2000 + n*100 + tid] = (float)slb[p];
        out[2400 + n*100 + tid] = (tv > 0.f) ? 1.f : 0.f;
    }
}

extern "C" void kernel_launch(void* const* d_in, const int* in_sizes, int n_in,
                              void* d_out, int out_size) {
    const float *cls[3], *gau[3];
    if (in_sizes[0] == in_sizes[1]) {          // interleaved
        cls[0]=(const float*)d_in[0]; gau[0]=(const float*)d_in[1];
        cls[1]=(const float*)d_in[2]; gau[1]=(const float*)d_in[3];
        cls[2]=(const float*)d_in[4]; gau[2]=(const float*)d_in[5];
    } else {                                   // grouped
        cls[0]=(const float*)d_in[0]; cls[1]=(const float*)d_in[1]; cls[2]=(const float*)d_in[2];
        gau[0]=(const float*)d_in[3]; gau[1]=(const float*)d_in[4]; gau[2]=(const float*)d_in[5];
    }
    float* out = (float*)d_out;

    k_score_all<<<8400, 256>>>(cls[0], gau[0], cls[1], gau[1], cls[2], gau[2]);
    k_histA<<<NIMG * 3 * NSLICE, 256>>>();
    k_thresh<<<NIMG * 3, 1024>>>();
    k_collect<<<NIMG * 3 * NSLICE, 256>>>();
    k_final<<<NIMG * 3, 1024>>>(gau[0], gau[1], gau[2]);
    k_nms<<<NIMG, 1024>>>(out);
}

// round 16
// speedup vs baseline: 1.2091x; 1.0144x over previous
#include <cuda_runtime.h>
#include <cstdint>

#define NIMG  4
#define CCH   80
#define TOPN  500
#define NCAND 1500
#define CAP0 524288
#define CAP1 131072
#define CAP2 65536
#define CAPI (CAP0+CAP1+CAP2)
#define NSLICE 16
#define NBIN2 8192
#define BOX_LOGIT_THRESH (-2.9444389791664403f)

__device__ __align__(16) unsigned long long g_cand[NIMG * CAPI];
__device__ unsigned int       g_cnt[NIMG * 3];
__device__ unsigned int       g_hist2[NIMG * 3 * NBIN2];
__device__ __align__(16) unsigned long long g_selbuf[NIMG * 3 * 4096];
__device__ unsigned int       g_selcnt[NIMG * 3];
__device__ unsigned int       g_T8[NIMG * 3];
__device__ unsigned long long g_top[NIMG * NCAND];
__device__ float g_x1[NIMG*NCAND], g_y1[NIMG*NCAND], g_x2[NIMG*NCAND], g_y2[NIMG*NCAND];
__device__ int   g_lb[NIMG*NCAND];
__device__ unsigned char g_vd[NIMG*NCAND];

__constant__ int c_cap[3]  = {CAP0, CAP1, CAP2};
__constant__ int c_loff[3] = {0, CAP0, CAP0 + CAP1};

__device__ __forceinline__ float sigm(float x) {
    if (x >= 0.f) return 1.f / (1.f + expf(-x));
    float e = expf(x); return e / (1.f + e);
}

// hybrid bitonic descending sort, SZ elements, 1024 threads.
template<int SZ>
__device__ void bitonic_desc_h(unsigned long long* a) {
    constexpr int E = SZ / 1024;
    int tid = threadIdx.x;
    unsigned long long v[E];
    #pragma unroll
    for (int m = 0; m < E; m++) v[m] = a[tid + (m << 10)];
    #pragma unroll
    for (int k = 2; k <= 32; k <<= 1) {
        #pragma unroll
        for (int j = k >> 1; j >= 1; j >>= 1) {
            #pragma unroll
            for (int m = 0; m < E; m++) {
                int t = tid + (m << 10);
                unsigned long long pv = __shfl_xor_sync(0xFFFFFFFFu, v[m], j);
                bool keepmax = (((t & k) == 0) == ((t & j) == 0));
                if (keepmax == (pv > v[m])) v[m] = pv;
            }
        }
    }
    #pragma unroll
    for (int m = 0; m < E; m++) a[tid + (m << 10)] = v[m];
    __syncthreads();
    for (int k = 64; k <= SZ; k <<= 1) {
        for (int j = k >> 1; j >= 32; j >>= 1) {
            #pragma unroll
            for (int m = 0; m < E; m++) {
                int t = tid + (m << 10);
                int ixj = t ^ j;
                if (ixj > t) {
                    unsigned long long u = a[t], w = a[ixj];
                    bool sw = ((t & k) == 0) ? (u < w) : (u > w);
                    if (sw) { a[t] = w; a[ixj] = u; }
                }
            }
            __syncthreads();
        }
        #pragma unroll
        for (int m = 0; m < E; m++) v[m] = a[tid + (m << 10)];
        #pragma unroll
        for (int j = 16; j >= 1; j >>= 1) {
            #pragma unroll
            for (int m = 0; m < E; m++) {
                int t = tid + (m << 10);
                unsigned long long pv = __shfl_xor_sync(0xFFFFFFFFu, v[m], j);
                bool keepmax = (((t & k) == 0) == ((t & j) == 0));
                if (keepmax == (pv > v[m])) v[m] = pv;
            }
        }
        #pragma unroll
        for (int m = 0; m < E; m++) a[tid + (m << 10)] = v[m];
        __syncthreads();
    }
}

// warp-aggregated candidate emit (up to 8 per thread)
template<int LVL, int CAPL, int LOFF>
__device__ __forceinline__ void emit8(int n, const unsigned* sbv, const int* rrv, int cnt) {
    int lane = threadIdx.x & 31;
    unsigned cinc = (unsigned)cnt;
    #pragma unroll
    for (int off = 1; off < 32; off <<= 1) {
        unsigned t = __shfl_up_sync(0xFFFFFFFFu, cinc, off);
        if (lane >= off) cinc += t;
    }
    unsigned total = __shfl_sync(0xFFFFFFFFu, cinc, 31);
    if (total == 0u) return;
    int b = n * 3 + LVL;
    unsigned base = 0;
    if (lane == 0) base = atomicAdd(&g_cnt[b], total);
    base = __shfl_sync(0xFFFFFFFFu, base, 0);
    unsigned pre = cinc - (unsigned)cnt;
    #pragma unroll
    for (int k = 0; k < 8; k++) {
        if (k >= cnt) break;
        unsigned slot = base + pre + (unsigned)k;
        if (slot < (unsigned)CAPL)
            g_cand[(size_t)n * CAPI + LOFF + slot] =
                ((unsigned long long)sbv[k] << 32) | (unsigned)(~rrv[k]);
    }
}

#define CAND_CHECK(px, cl, gc, m) do {                                       \
    if ((px) && ((gc) >= (m))) {                                             \
        float sc_ = sqrtf(sigm(cl) * sigm(gc));                              \
        sbv[cnt] = __float_as_uint(sc_); rrv[cnt] = rb + _k; cnt++;          \
    } _k++;                                                                  \
} while (0)

#define STENCIL8_BODY(s0, s1, s2)                                            \
    float4 uA = *(const float4*)(s0), uB = *(const float4*)((s0) + 4);       \
    float4 cA = *(const float4*)(s1), cB = *(const float4*)((s1) + 4);       \
    float4 dA = *(const float4*)(s2), dB = *(const float4*)((s2) + 4);       \
    float cmL = hasL ? fmaxf(fmaxf((s0)[-1], (s1)[-1]), (s2)[-1]) : 0.f;     \
    float cmR = hasR ? fmaxf(fmaxf((s0)[8],  (s1)[8]),  (s2)[8])  : 0.f;     \
    float4 mA, mB;                                                           \
    mA.x = fmaxf(fmaxf(uA.x, cA.x), dA.x);                                   \
    mA.y = fmaxf(fmaxf(uA.y, cA.y), dA.y);                                   \
    mA.z = fmaxf(fmaxf(uA.z, cA.z), dA.z);                                   \
    mA.w = fmaxf(fmaxf(uA.w, cA.w), dA.w);                                   \
    mB.x = fmaxf(fmaxf(uB.x, cB.x), dB.x);                                   \
    mB.y = fmaxf(fmaxf(uB.y, cB.y), dB.y);                                   \
    mB.z = fmaxf(fmaxf(uB.z, cB.z), dB.z);                                   \
    mB.w = fmaxf(fmaxf(uB.w, cB.w), dB.w);                                   \
    float m0 = fmaxf(fmaxf(cmL,  mA.x), mA.y);                               \
    float m1 = fmaxf(fmaxf(mA.x, mA.y), mA.z);                               \
    float m2 = fmaxf(fmaxf(mA.y, mA.z), mA.w);                               \
    float m3 = fmaxf(fmaxf(mA.z, mA.w), mB.x);                               \
    float m4 = fmaxf(fmaxf(mA.w, mB.x), mB.y);                               \
    float m5 = fmaxf(fmaxf(mB.x, mB.y), mB.z);                               \
    float m6 = fmaxf(fmaxf(mB.y, mB.z), mB.w);                               \
    float m7 = fmaxf(fmaxf(mB.z, mB.w), cmR);                                \
    int _k = 0;                                                              \
    CAND_CHECK(p0, clA.x, cA.x, m0);                                         \
    CAND_CHECK(p1, clA.y, cA.y, m1);                                         \
    CAND_CHECK(p2, clA.z, cA.z, m2);                                         \
    CAND_CHECK(p3, clA.w, cA.w, m3);                                         \
    CAND_CHECK(p4, clB.x, cB.x, m4);                                         \
    CAND_CHECK(p5, clB.y, cB.y, m5);                                         \
    CAND_CHECK(p6, clB.z, cB.z, m6);                                         \
    CAND_CHECK(p7, clB.w, cB.w, m7);

template<int H, int W, int R, int LVL, int CAPL, int LOFF>
__device__ __forceinline__ void score_tile8(const float* __restrict__ cls,
                                            const float* __restrict__ gau,
                                            float* sg, int bid) {
    constexpr int hw  = H * W;
    constexpr int RPC = H / R;
    constexpr int w4  = W / 4;
    constexpr int NF4 = (R + 2) * w4;
    int tid = threadIdx.x;
    int cb  = bid / RPC;
    int ry  = (bid - cb * RPC) * R;
    int n   = cb / CCH;
    size_t base = (size_t)cb * hw;

    for (int i = tid; i < NF4; i += 256) {
        int row = i / w4;
        int c4  = i - row * w4;
        int gy  = min(max(ry - 1 + row, 0), H - 1);
        ((float4*)sg)[i] = *(const float4*)(gau + base + (size_t)gy * W + c4 * 4);
    }
    __syncthreads();

    int t  = tid * 8;
    int lr = t / W;
    int x0 = t - lr * W;
    int y  = ry + lr;
    int sr = lr + 1;

    const float* cp = cls + base + (size_t)y * W + x0;
    float4 clA = *(const float4*)cp;
    float4 clB = *(const float4*)(cp + 4);
    bool iy = (y > 0) & (y < H - 1);
    bool hasL = x0 > 0, hasR = x0 < W - 8;
    bool p0 = iy && hasL && (clA.x > BOX_LOGIT_THRESH);
    bool p1 = iy && (clA.y > BOX_LOGIT_THRESH);
    bool p2 = iy && (clA.z > BOX_LOGIT_THRESH);
    bool p3 = iy && (clA.w > BOX_LOGIT_THRESH);
    bool p4 = iy && (clB.x > BOX_LOGIT_THRESH);
    bool p5 = iy && (clB.y > BOX_LOGIT_THRESH);
    bool p6 = iy && (clB.z > BOX_LOGIT_THRESH);
    bool p7 = iy && hasR && (clB.w > BOX_LOGIT_THRESH);

    unsigned sbv[8]; int rrv[8]; int cnt = 0;
    int rb = (cb - n * CCH) * hw + y * W + x0;

    if (p0 | p1 | p2 | p3 | p4 | p5 | p6 | p7) {
        const float* s0 = sg + (sr - 1) * W + x0;
        const float* s1 = sg + sr * W + x0;
        const float* s2 = sg + (sr + 1) * W + x0;
        STENCIL8_BODY(s0, s1, s2)
    }
    emit8<LVL, CAPL, LOFF>(n, sbv, rrv, cnt);
}

template<int H, int W, int LVL, int CAPL, int LOFF>
__device__ __forceinline__ void score_body8(const float* __restrict__ cls,
                                            const float* __restrict__ gau, int bid) {
    constexpr int hw  = H * W;
    constexpr int CHW = CCH * hw;
    constexpr int OPI = CHW / 8;
    int q   = bid * 256 + threadIdx.x;
    int n   = q / OPI;
    int pix = q * 8;
    int r   = pix - n * CHW;
    int pp  = r % hw;
    int y   = pp / W;
    int x0  = pp & (W - 1);

    const float* cp = cls + (size_t)pix;
    float4 clA = *(const float4*)cp;
    float4 clB = *(const float4*)(cp + 4);
    bool iy = (y > 0) & (y < H - 1);
    bool hasL = x0 > 0, hasR = x0 < W - 8;
    bool p0 = iy && hasL && (clA.x > BOX_LOGIT_THRESH);
    bool p1 = iy && (clA.y > BOX_LOGIT_THRESH);
    bool p2 = iy && (clA.z > BOX_LOGIT_THRESH);
    bool p3 = iy && (clA.w > BOX_LOGIT_THRESH);
    bool p4 = iy && (clB.x > BOX_LOGIT_THRESH);
    bool p5 = iy && (clB.y > BOX_LOGIT_THRESH);
    bool p6 = iy && (clB.z > BOX_LOGIT_THRESH);
    bool p7 = iy && hasR && (clB.w > BOX_LOGIT_THRESH);

    unsigned sbv[8]; int rrv[8]; int cnt = 0;
    int rb = r;

    if (p0 | p1 | p2 | p3 | p4 | p5 | p6 | p7) {
        const float* Gb = gau + (size_t)(pix - pp);
        const float* s0 = Gb + pp - W;
        const float* s1 = Gb + pp;
        const float* s2 = Gb + pp + W;
        STENCIL8_BODY(s0, s1, s2)
    }
    emit8<LVL, CAPL, LOFF>(n, sbv, rrv, cnt);
}

__global__ void __launch_bounds__(256, 6) k_score_all(
    const float* __restrict__ c0, const float* __restrict__ g0,
    const float* __restrict__ c1, const float* __restrict__ g1,
    const float* __restrict__ c2, const float* __restrict__ g2) {
    __shared__ __align__(16) float sg[10 * 256];
    int bid = blockIdx.x;
    if (bid < 6400)       score_tile8<160,256,8, 0,CAP0,0>   (c0, g0, sg, bid);
    else if (bid < 8000)  score_tile8<80, 128,16,1,CAP1,CAP0>(c1, g1, sg, bid - 6400);
    else                  score_body8<40, 64, 2,CAP2,CAP0+CAP1>(c2, g2, bid - 8000);
}

// phase A: slice-parallel coarse histogram (key>>49, 8192 bins), 4 elems/thread/iter (MLP)
__global__ void __launch_bounds__(256) k_histA() {
    int blk = blockIdx.x;
    int b = blk >> 4, s = blk & (NSLICE - 1);
    int lvl = b % 3, n = b / 3;
    __shared__ unsigned int h[NBIN2];
    for (int i = threadIdx.x; i < NBIN2; i += 256) h[i] = 0;
    __syncthreads();
    unsigned cnt = min(g_cnt[b], (unsigned)c_cap[lvl]);
    const unsigned long long* cand = &g_cand[(size_t)n * CAPI + c_loff[lvl]];
    unsigned lo = (unsigned)(((unsigned long long)s * cnt) >> 4);
    unsigned hi = (unsigned)(((unsigned long long)(s + 1) * cnt) >> 4);
    for (unsigned base = lo + threadIdx.x * 4u; base < hi; base += 1024u) {
        unsigned long long k0 = 0, k1 = 0, k2 = 0, k3 = 0;
        bool i0 = base < hi, i1 = base + 1 < hi, i2 = base + 2 < hi, i3 = base + 3 < hi;
        if (i0) k0 = cand[base];
        if (i1) k1 = cand[base + 1];
        if (i2) k2 = cand[base + 2];
        if (i3) k3 = cand[base + 3];
        if (i0) atomicAdd(&h[(unsigned)(k0 >> 49)], 1u);
        if (i1) atomicAdd(&h[(unsigned)(k1 >> 49)], 1u);
        if (i2) atomicAdd(&h[(unsigned)(k2 >> 49)], 1u);
        if (i3) atomicAdd(&h[(unsigned)(k3 >> 49)], 1u);
    }
    __syncthreads();
    for (int i = threadIdx.x; i < NBIN2; i += 256)
        if (h[i]) atomicAdd(&g_hist2[(size_t)b * NBIN2 + i], h[i]);
}

// phase B: per-(n,lvl) threshold bin from suffix sums; zeroes hist + selcnt
__global__ void __launch_bounds__(1024) k_thresh() {
    int b = blockIdx.x;
    __shared__ unsigned int bh[NBIN2];
    __shared__ unsigned int tot[1024];
    int tid = threadIdx.x;
    unsigned int* H = &g_hist2[(size_t)b * NBIN2];
    unsigned v[8];
    #pragma unroll
    for (int m = 0; m < 8; m++) v[m] = H[tid * 8 + m];
    #pragma unroll
    for (int m = 0; m < 8; m++) H[tid * 8 + m] = 0;   // ready for next replay
    unsigned acc = 0;
    #pragma unroll
    for (int m = 7; m >= 0; m--) { acc += v[m]; v[m] = acc; }
    tot[tid] = acc;
    if (tid == 0) { g_T8[b] = 0; g_selcnt[b] = 0; }
    __syncthreads();
    for (int off = 1; off < 1024; off <<= 1) {
        unsigned t = tot[tid];
        if (tid + off < 1024) t += tot[tid + off];
        __syncthreads();
        tot[tid] = t;
        __syncthreads();
    }
    unsigned later = (tid == 1023) ? 0u : tot[tid + 1];
    #pragma unroll
    for (int m = 0; m < 8; m++) bh[tid * 8 + m] = v[m] + later;
    __syncthreads();
    #pragma unroll
    for (int m = 0; m < 8; m++) {
        int i = tid * 8 + m;
        unsigned si = bh[i];
        unsigned sn = (i == NBIN2 - 1) ? 0u : bh[i + 1];
        if (si >= (unsigned)TOPN && sn < (unsigned)TOPN) g_T8[b] = (unsigned)i;
    }
}

// phase C: slice-parallel collect (4 elems/thread/iter, direct atomic append — takes are rare)
__global__ void __launch_bounds__(256) k_collect() {
    int blk = blockIdx.x;
    int b = blk >> 4, s = blk & (NSLICE - 1);
    int lvl = b % 3, n = b / 3;
    unsigned cnt = min(g_cnt[b], (unsigned)c_cap[lvl]);
    unsigned T8 = g_T8[b];
    const unsigned long long* cand = &g_cand[(size_t)n * CAPI + c_loff[lvl]];
    unsigned lo = (unsigned)(((unsigned long long)s * cnt) >> 4);
    unsigned hi = (unsigned)(((unsigned long long)(s + 1) * cnt) >> 4);
    unsigned long long* sb_ = &g_selbuf[(size_t)b * 4096];
    for (unsigned base = lo + threadIdx.x * 4u; base < hi; base += 1024u) {
        unsigned long long k0 = 0, k1 = 0, k2 = 0, k3 = 0;
        bool i0 = base < hi, i1 = base + 1 < hi, i2 = base + 2 < hi, i3 = base + 3 < hi;
        if (i0) k0 = cand[base];
        if (i1) k1 = cand[base + 1];
        if (i2) k2 = cand[base + 2];
        if (i3) k3 = cand[base + 3];
        if (i0 && (unsigned)(k0 >> 49) >= T8) {
            unsigned p = atomicAdd(&g_selcnt[b], 1u);
            if (p < 4096u) sb_[p] = k0;
        }
        if (i1 && (unsigned)(k1 >> 49) >= T8) {
            unsigned p = atomicAdd(&g_selcnt[b], 1u);
            if (p < 4096u) sb_[p] = k1;
        }
        if (i2 && (unsigned)(k2 >> 49) >= T8) {
            unsigned p = atomicAdd(&g_selcnt[b], 1u);
            if (p < 4096u) sb_[p] = k2;
        }
        if (i3 && (unsigned)(k3 >> 49) >= T8) {
            unsigned p = atomicAdd(&g_selcnt[b], 1u);
            if (p < 4096u) sb_[p] = k3;
        }
    }
}

// phase D: sort collected keys, emit top-500 + fused box solve; resets g_cnt
__global__ void __launch_bounds__(1024) k_final(const float* __restrict__ g0,
                                                const float* __restrict__ g1,
                                                const float* __restrict__ g2) {
    int b = blockIdx.x;
    int n = b / 3, lvl = b % 3;
    __shared__ unsigned long long sel[4096];
    int tid = threadIdx.x;
    unsigned mN = min(g_selcnt[b], 4096u);
    if (tid == 0) g_cnt[b] = 0;   // reset for next graph replay
    const unsigned long long* sb_ = &g_selbuf[(size_t)b * 4096];
    for (int i = tid; i < 4096; i += 1024)
        sel[i] = ((unsigned)i < mN) ? sb_[i] : 0ull;
    __syncthreads();
    bitonic_desc_h<4096>(sel);

    if (tid < TOPN) {
        int t = n * NCAND + lvl * TOPN + tid;
        unsigned long long key = sel[tid];
        g_top[t] = key;

        int H, W, step; const float* G;
        if (lvl == 0)      { H = 160; W = 256; step = 8;  G = g0; }
        else if (lvl == 1) { H = 80;  W = 128; step = 16; G = g1; }
        else               { H = 40;  W = 64;  step = 32; G = g2; }
        float sc = __uint_as_float((unsigned)(key >> 32));
        unsigned flat = ~(unsigned)key;
        int hw = H * W;
        if (!(sc > 0.f) || flat >= (unsigned)(CCH * hw)) {
            g_x1[t]=0.f; g_y1[t]=0.f; g_x2[t]=0.f; g_y2[t]=0.f; g_lb[t]=1; g_vd[t]=0;
        } else {
            int c = (int)(flat / hw);
            int rem = (int)(flat - (unsigned)c * hw);
            int y = rem / W, x = rem - y * W;
            const float* Bp = G + ((size_t)(n * CCH + c)) * hw;
            auto LV = [&](int yy, int xx) -> float {
                yy = min(max(yy, 0), H - 1);
                xx = min(max(xx, 0), W - 1);
                return log1pf(expf(-Bp[yy * W + xx])) * 0.125f;
            };
            float l0 = LV(y, x);
            float lxp = LV(y, x+1), lxm = LV(y, x-1);
            float lyp = LV(y+1, x), lym = LV(y-1, x);
            float Ax = (lxp + lxm - 2.f * l0) * 0.5f;
            float Ay = (lyp + lym - 2.f * l0) * 0.5f;
            bool px = Ax > 1e-8f, py = Ay > 1e-8f;
            float Axs = px ? Ax : 1.f, Ays = py ? Ay : 1.f;
            float mux = (float)x - (lxp - lxm) / (4.f * Axs);
            float muy = (float)y - (lyp - lym) / (4.f * Ays);
            float wb = (px ? rsqrtf(2.f * Axs) : 0.f) * (float)step;
            float hb = (py ? rsqrtf(2.f * Ays) : 0.f) * (float)step;
            float x1 = mux * (float)step - 0.5f * wb + (float)(step - 1) * 0.5f;
            float y1 = muy * (float)step - 0.5f * hb + (float)(step - 1) * 0.5f;
            bool vd = (wb > 0.f) && (hb > 0.f);
            float x2 = x1 + wb - 1.f, y2 = y1 + hb - 1.f;
            g_x1[t] = fminf(fmaxf(x1, 0.f), 2047.f);
            g_x2[t] = fminf(fmaxf(x2, 0.f), 2047.f);
            g_y1[t] = fminf(fmaxf(y1, 0.f), 1279.f);
            g_y2[t] = fminf(fmaxf(y2, 0.f), 1279.f);
            g_lb[t] = c + 1; g_vd[t] = vd ? 1 : 0;
        }
    }
}

// per-image NMS: hybrid sort, then exact per-class greedy (one warp per class)
__global__ void __launch_bounds__(1024) k_nms(float* __restrict__ out) {
    __shared__ unsigned long long skey[2048];
    __shared__ float bx1[NCAND], by1[NCAND], bx2[NCAND], by2[NCAND];
    __shared__ short slb[NCAND];
    __shared__ unsigned char keep[NCAND];
    __shared__ short cls_list[NCAND];
    __shared__ int   ofs[82];
    __shared__ int   s_ti[100];
    int n = blockIdx.x, tid = threadIdx.x;
    int w = tid >> 5, lane = tid & 31;

    for (int p = tid; p < 2048; p += 1024) {
        unsigned long long kk = 0ull;
        if (p < NCAND) {
            int gi = n * NCAND + p;
            float sc = __uint_as_float((unsigned)(g_top[gi] >> 32));
            float sv = g_vd[gi] ? sc : -1.f;
            unsigned bits = __float_as_uint(sv);
            unsigned ord = (bits & 0x80000000u) ? ~bits : (bits | 0x80000000u);
            kk = ((unsigned long long)ord << 32) | (0xFFFFFFFFu - (unsigned)p);
        }
        skey[p] = kk;
    }
    __syncthreads();
    bitonic_desc_h<2048>(skey);

    for (int p = tid; p < NCAND; p += 1024) {
        int pos = (int)(0xFFFFFFFFu - (unsigned)skey[p]);
        int gi = n * NCAND + pos;
        bx1[p]=g_x1[gi]; by1[p]=g_y1[gi]; bx2[p]=g_x2[gi]; by2[p]=g_y2[gi];
        slb[p]=(short)g_lb[gi]; keep[p]=g_vd[gi];
    }
    if (tid < 82) ofs[tid] = 0;
    __syncthreads();

    for (int p = tid; p < NCAND; p += 1024)
        if (keep[p]) atomicAdd((unsigned*)&ofs[slb[p]], 1u);
    __syncthreads();
    if (tid == 0) {
        int acc = 0;
        for (int c = 1; c <= 80; c++) { int v = ofs[c]; ofs[c] = acc; acc += v; }
        ofs[81] = acc;
        ofs[0]  = 0;
    }
    __syncthreads();

    for (int lbl = w + 1; lbl <= 80; lbl += 32) {
        int start = ofs[lbl];
        int fill = 0;
        for (int base = 0; base < NCAND; base += 32) {
            int p = base + lane;
            bool match = (p < NCAND) && keep[p] && (slb[p] == (short)lbl);
            unsigned bal = __ballot_sync(0xFFFFFFFFu, match);
            if (match) {
                int pre = __popc(bal & ((1u << lane) - 1u));
                cls_list[start + fill + pre] = (short)p;
            }
            fill += __popc(bal);
        }
    }
    __syncthreads();

    for (int lbl = w + 1; lbl <= 80; lbl += 32) {
        int start = ofs[lbl];
        int k = ofs[lbl + 1] - start;
        if (k < 2) continue;
        for (int t0 = 0; t0 < k; t0 += 32) {
            int e = t0 + lane;
            bool in = e < k;
            int idx = in ? (int)cls_list[start + e] : 0;
            float x1 = 0, y1 = 0, x2 = 0, y2 = 0, ar = 1.f;
            bool alive = false;
            if (in) {
                x1 = bx1[idx]; y1 = by1[idx]; x2 = bx2[idx]; y2 = by2[idx];
                ar = (x2 - x1 + 1.f) * (y2 - y1 + 1.f);
                alive = keep[idx] != 0;
            }
            if (alive) {
                for (int qe = 0; qe < t0; qe++) {
                    int qi = (int)cls_list[start + qe];
                    if (!keep[qi]) continue;
                    float qx1 = bx1[qi], qy1 = by1[qi], qx2 = bx2[qi], qy2 = by2[qi];
                    float iw = fmaxf(fminf(x2, qx2) - fmaxf(x1, qx1) + 1.f, 0.f);
                    float ih = fmaxf(fminf(y2, qy2) - fmaxf(y1, qy1) + 1.f, 0.f);
                    float inter = iw * ih;
                    float qar = (qx2 - qx1 + 1.f) * (qy2 - qy1 + 1.f);
                    if (inter / (ar + qar - inter + 1e-9f) > 0.5f) { alive = false; break; }
                }
            }
            int lim = min(32, k - t0);
            unsigned sup = 0;
            for (int m = 0; m < lim - 1; m++) {
                float mx1 = __shfl_sync(0xFFFFFFFFu, x1, m);
                float my1 = __shfl_sync(0xFFFFFFFFu, y1, m);
                float mx2 = __shfl_sync(0xFFFFFFFFu, x2, m);
                float my2 = __shfl_sync(0xFFFFFFFFu, y2, m);
                float mar = __shfl_sync(0xFFFFFFFFu, ar, m);
                if (in && m < lane) {
                    float iw = fmaxf(fminf(x2, mx2) - fmaxf(x1, mx1) + 1.f, 0.f);
                    float ih = fmaxf(fminf(y2, my2) - fmaxf(y1, my1) + 1.f, 0.f);
                    float inter = iw * ih;
                    if (inter / (ar + mar - inter + 1e-9f) > 0.5f) sup |= (1u << m);
                }
            }
            for (int m = 0; m < lim - 1; m++) {
                unsigned bal = __ballot_sync(0xFFFFFFFFu, alive);
                if (lane > m && ((bal >> m) & 1u) && ((sup >> m) & 1u)) alive = false;
            }
            if (in) keep[idx] = alive ? 1 : 0;
        }
    }
    __syncthreads();

    if (tid < 32) {
        int cnt = 0;
        for (int pass = 0; pass < 2; pass++) {
            for (int b2 = 0; b2 < NCAND && cnt < 100; b2 += 32) {
                int i2 = b2 + lane;
                bool pr = (i2 < NCAND) && ((pass == 0) ? (keep[i2] != 0) : (keep[i2] == 0));
                unsigned ww = __ballot_sync(0xFFFFFFFFu, pr);
                int pre = __popc(ww & ((1u << lane) - 1u));
                if (pr && cnt + pre < 100) s_ti[cnt + pre] = i2;
                cnt += __popc(ww);
            }
            if (cnt > 100) cnt = 100;
        }
    }
    __syncthreads();

    if (tid < 100) {
        int p = s_ti[tid];
        unsigned ord = (unsigned)(skey[p] >> 32);
        float s = (ord & 0x80000000u) ? __uint_as_float(ord ^ 0x80000000u)
                                      : __uint_as_float(~ord);
        float tv = keep[p] ? s : -1.f;
        out[n*400 + tid*4 + 0] = bx1[p];
        out[n*400 + tid*4 + 1] = by1[p];
        out[n*400 + tid*4 + 2] = bx2[p];
        out[n*400 + tid*4 + 3] = by2[p];
        out[1600 + n*100 + tid] = tv;
        out[2000 + n*100 + tid] = (float)slb[p];
        out[2400 + n*100 + tid] = (tv > 0.f) ? 1.f : 0.f;
    }
}

extern "C" void kernel_launch(void* const* d_in, const int* in_sizes, int n_in,
                              void* d_out, int out_size) {
    const float *cls[3], *gau[3];
    if (in_sizes[0] == in_sizes[1]) {          // interleaved
        cls[0]=(const float*)d_in[0]; gau[0]=(const float*)d_in[1];
        cls[1]=(const float*)d_in[2]; gau[1]=(const float*)d_in[3];
        cls[2]=(const float*)d_in[4]; gau[2]=(const float*)d_in[5];
    } else {                                   // grouped
        cls[0]=(const float*)d_in[0]; cls[1]=(const float*)d_in[1]; cls[2]=(const float*)d_in[2];
        gau[0]=(const float*)d_in[3]; gau[1]=(const float*)d_in[4]; gau[2]=(const float*)d_in[5];
    }
    float* out = (float*)d_out;

    k_score_all<<<8400, 256>>>(cls[0], gau[0], cls[1], gau[1], cls[2], gau[2]);
    k_histA<<<NIMG * 3 * NSLICE, 256>>>();
    k_thresh<<<NIMG * 3, 1024>>>();
    k_collect<<<NIMG * 3 * NSLICE, 256>>>();
    k_final<<<NIMG * 3, 1024>>>(gau[0], gau[1], gau[2]);
    k_nms<<<NIMG, 1024>>>(out);
}